// round 3
// baseline (speedup 1.0000x reference)
#include <cuda_runtime.h>
#include <math.h>
#include <stdint.h>

#define N_TABLES 26
#define ROWS 100001
#define D 64
#define BATCH 8192
#define L 4
#define NFEAT 27
#define FEAT_LD (NFEAT * D)  // 1728
#define NPAIR 351
#define RWIDTH 415

// ---------------- scratch (device globals) ----------------------------------
__device__ float g_b0[BATCH * 512];
__device__ float g_b1[BATCH * 256];
__device__ float g_feat[BATCH * FEAT_LD];
__device__ float g_R[BATCH * RWIDTH];
__device__ float g_t0[BATCH * 512];
__device__ float g_t1[BATCH * 256];

__device__ __forceinline__ float to_tf32(float v) {
    float r;
    asm("cvt.rna.tf32.f32 %0, %1;" : "=f"(r) : "f"(v));
    return r;
}

// ---------------- pipelined tf32 tensor-core GEMM ----------------------------
// C[M,N] = act(A[M,K] * W[N,K]^T + bias)
// BM in {128,64}, BN=64, BK=32. THREADS = BM*2 (8 or 4 warps).
// Warp grid: (BM/32) m-warps x 2 n-warps, warp tile 32x32 = 2x4 m16n8k8.
// Double-buffered smem + register prefetch: one __syncthreads per K-iter.
#define ASTRIDE 36
template<int BM>
__global__ void __launch_bounds__(BM * 2)
gemm_tf32(const float* __restrict__ A, int lda,
          const float* __restrict__ W,  // [N,K] row-major
          const float* __restrict__ bias,
          float* __restrict__ C, int ldc,
          int M, int N, int K, int do_relu)
{
    constexpr int THREADS = BM * 2;
    constexpr int NA = BM * 32 / THREADS;   // 16
    constexpr int NB = 64 * 32 / THREADS;   // 8 (BM=128) or 16 (BM=64)

    __shared__ float As[2][BM * ASTRIDE];
    __shared__ float Bs[2][64 * ASTRIDE];

    const int tid = threadIdx.x;
    const int warp = tid >> 5;
    const int lane = tid & 31;
    const int wm = warp >> 1;
    const int wn = warp & 1;
    const int g = lane >> 2;
    const int c = lane & 3;
    const int bm = blockIdx.y * BM;
    const int bn = blockIdx.x * 64;

    float acc[2][4][4];
#pragma unroll
    for (int mt = 0; mt < 2; mt++)
#pragma unroll
        for (int nt = 0; nt < 4; nt++)
#pragma unroll
            for (int q = 0; q < 4; q++) acc[mt][nt][q] = 0.f;

    float ra[NA], rb[NB];
    const int KT = (K + 31) / 32;

    // ---- prologue: tile 0 -> regs -> smem[0]
#pragma unroll
    for (int i = 0; i < NA; i++) {
        int idx = i * THREADS + tid;
        int m = idx >> 5, k = idx & 31;
        ra[i] = (k < K) ? A[(size_t)(bm + m) * lda + k] : 0.f;
    }
#pragma unroll
    for (int i = 0; i < NB; i++) {
        int idx = i * THREADS + tid;
        int n = idx >> 5, k = idx & 31;
        rb[i] = (k < K) ? W[(size_t)(bn + n) * K + k] : 0.f;
    }
#pragma unroll
    for (int i = 0; i < NA; i++) {
        int idx = i * THREADS + tid;
        As[0][(idx >> 5) * ASTRIDE + (idx & 31)] = to_tf32(ra[i]);
    }
#pragma unroll
    for (int i = 0; i < NB; i++) {
        int idx = i * THREADS + tid;
        Bs[0][(idx >> 5) * ASTRIDE + (idx & 31)] = to_tf32(rb[i]);
    }
    __syncthreads();

    for (int kt = 0; kt < KT; kt++) {
        const int cur = kt & 1;
        const int k0n = (kt + 1) * 32;

        // prefetch next tile into registers (overlaps with compute below)
        if (kt + 1 < KT) {
#pragma unroll
            for (int i = 0; i < NA; i++) {
                int idx = i * THREADS + tid;
                int m = idx >> 5, k = k0n + (idx & 31);
                ra[i] = (k < K) ? A[(size_t)(bm + m) * lda + k] : 0.f;
            }
#pragma unroll
            for (int i = 0; i < NB; i++) {
                int idx = i * THREADS + tid;
                int n = idx >> 5, k = k0n + (idx & 31);
                rb[i] = (k < K) ? W[(size_t)(bn + n) * K + k] : 0.f;
            }
        }

        // compute from smem[cur]
        const float* as = As[cur];
        const float* bs = Bs[cur];
#pragma unroll
        for (int ks = 0; ks < 4; ks++) {
            const int kk = ks * 8;
            uint32_t a[2][4], b[4][2];
#pragma unroll
            for (int mt = 0; mt < 2; mt++) {
                int mb = wm * 32 + mt * 16;
                a[mt][0] = __float_as_uint(as[(mb + g) * ASTRIDE + kk + c]);
                a[mt][1] = __float_as_uint(as[(mb + g + 8) * ASTRIDE + kk + c]);
                a[mt][2] = __float_as_uint(as[(mb + g) * ASTRIDE + kk + c + 4]);
                a[mt][3] = __float_as_uint(as[(mb + g + 8) * ASTRIDE + kk + c + 4]);
            }
#pragma unroll
            for (int nt = 0; nt < 4; nt++) {
                int nb = wn * 32 + nt * 8;
                b[nt][0] = __float_as_uint(bs[(nb + g) * ASTRIDE + kk + c]);
                b[nt][1] = __float_as_uint(bs[(nb + g) * ASTRIDE + kk + c + 4]);
            }
#pragma unroll
            for (int mt = 0; mt < 2; mt++)
#pragma unroll
                for (int nt = 0; nt < 4; nt++) {
                    asm volatile(
                        "mma.sync.aligned.m16n8k8.row.col.f32.tf32.tf32.f32 "
                        "{%0,%1,%2,%3}, {%4,%5,%6,%7}, {%8,%9}, {%0,%1,%2,%3};\n"
                        : "+f"(acc[mt][nt][0]), "+f"(acc[mt][nt][1]),
                          "+f"(acc[mt][nt][2]), "+f"(acc[mt][nt][3])
                        : "r"(a[mt][0]), "r"(a[mt][1]), "r"(a[mt][2]), "r"(a[mt][3]),
                          "r"(b[nt][0]), "r"(b[nt][1]));
                }
        }

        // store prefetched tile into the other buffer
        if (kt + 1 < KT) {
            float* asn = As[cur ^ 1];
            float* bsn = Bs[cur ^ 1];
#pragma unroll
            for (int i = 0; i < NA; i++) {
                int idx = i * THREADS + tid;
                asn[(idx >> 5) * ASTRIDE + (idx & 31)] = to_tf32(ra[i]);
            }
#pragma unroll
            for (int i = 0; i < NB; i++) {
                int idx = i * THREADS + tid;
                bsn[(idx >> 5) * ASTRIDE + (idx & 31)] = to_tf32(rb[i]);
            }
            __syncthreads();
        }
    }

    // ---- epilogue
#pragma unroll
    for (int mt = 0; mt < 2; mt++) {
        int row0 = bm + wm * 32 + mt * 16 + g;
#pragma unroll
        for (int nt = 0; nt < 4; nt++) {
            int col = bn + wn * 32 + nt * 8 + c * 2;
            float b0 = bias[col], b1 = bias[col + 1];
            float v0 = acc[mt][nt][0] + b0;
            float v1 = acc[mt][nt][1] + b1;
            float v2 = acc[mt][nt][2] + b0;
            float v3 = acc[mt][nt][3] + b1;
            if (do_relu) {
                v0 = fmaxf(v0, 0.f); v1 = fmaxf(v1, 0.f);
                v2 = fmaxf(v2, 0.f); v3 = fmaxf(v3, 0.f);
            }
            *(float2*)&C[(size_t)row0 * ldc + col] = make_float2(v0, v1);
            *(float2*)&C[(size_t)(row0 + 8) * ldc + col] = make_float2(v2, v3);
        }
    }
}

// ---------------- embedding gather + mean over L=4 ---------------------------
__global__ void __launch_bounds__(256)
embed_mean(const float* __restrict__ tables, const int* __restrict__ lS_i,
           float* __restrict__ feat)
{
    int gw = (blockIdx.x * blockDim.x + threadIdx.x) >> 5;
    int lane = threadIdx.x & 31;
    if (gw >= N_TABLES * BATCH) return;
    int t = gw / BATCH;
    int b = gw - t * BATCH;

    const int* idx = lS_i + (size_t)t * BATCH * L + (size_t)b * L;
    const float* tab = tables + (size_t)t * ROWS * D;

    int i0 = idx[0], i1 = idx[1], i2 = idx[2], i3 = idx[3];
    float2 v0 = ((const float2*)(tab + (size_t)i0 * D))[lane];
    float2 v1 = ((const float2*)(tab + (size_t)i1 * D))[lane];
    float2 v2 = ((const float2*)(tab + (size_t)i2 * D))[lane];
    float2 v3 = ((const float2*)(tab + (size_t)i3 * D))[lane];

    float sx = (v0.x + v1.x) + (v2.x + v3.x);
    float sy = (v0.y + v1.y) + (v2.y + v3.y);
    float2* out = (float2*)(feat + (size_t)b * FEAT_LD + (size_t)(1 + t) * D);
    out[lane] = make_float2(sx * 0.25f, sy * 0.25f);
}

// ---------------- pairwise interaction ---------------------------------------
#define TSTRIDE 65
__global__ void __launch_bounds__(128)
interact(const float* __restrict__ feat, float* __restrict__ R)
{
    __shared__ float T[NFEAT * TSTRIDE];
    int b = blockIdx.x;
    const float* f = feat + (size_t)b * FEAT_LD;
    for (int i = threadIdx.x; i < FEAT_LD; i += 128) {
        int fi = i >> 6, k = i & 63;
        T[fi * TSTRIDE + k] = f[i];
    }
    __syncthreads();

    float* r = R + (size_t)b * RWIDTH;
    for (int i = threadIdx.x; i < D; i += 128) r[i] = T[i];

    for (int p = threadIdx.x; p < NPAIR; p += 128) {
        int i = (int)floorf((sqrtf(8.f * (float)p + 1.f) + 1.f) * 0.5f);
        while (i * (i - 1) / 2 > p) i--;
        while ((i + 1) * i / 2 <= p) i++;
        int j = p - i * (i - 1) / 2;

        const float* ti = &T[i * TSTRIDE];
        const float* tj = &T[j * TSTRIDE];
        float s = 0.f;
#pragma unroll
        for (int k = 0; k < D; k++) s += ti[k] * tj[k];
        r[D + p] = s;
    }
}

// ---------------- final layer: [8192,256] x [256] + b ------------------------
__global__ void __launch_bounds__(256)
top_final(const float* __restrict__ A, const float* __restrict__ w,
          const float* __restrict__ bias, float* __restrict__ out)
{
    __shared__ float ws[256];
    int tid = threadIdx.x;
    ws[tid] = w[tid];
    __syncthreads();

    int warp = tid >> 5, lane = tid & 31;
    int row = blockIdx.x * 8 + warp;
    const float* a = A + (size_t)row * 256;
    float s = 0.f;
#pragma unroll
    for (int k = 0; k < 8; k++) s += a[lane + k * 32] * ws[lane + k * 32];
#pragma unroll
    for (int o = 16; o > 0; o >>= 1) s += __shfl_xor_sync(0xffffffffu, s, o);
    if (lane == 0) out[row] = s + bias[0];
}

// ---------------- launch ------------------------------------------------------
extern "C" void kernel_launch(void* const* d_in, const int* in_sizes, int n_in,
                              void* d_out, int out_size)
{
    const float* dense_x = (const float*)d_in[0];
    const int*   lS_i    = (const int*)d_in[2];
    const float* tables  = (const float*)d_in[3];
    const float* bw0 = (const float*)d_in[4];
    const float* bb0 = (const float*)d_in[5];
    const float* bw1 = (const float*)d_in[6];
    const float* bb1 = (const float*)d_in[7];
    const float* bw2 = (const float*)d_in[8];
    const float* bb2 = (const float*)d_in[9];
    const float* tw0 = (const float*)d_in[10];
    const float* tb0 = (const float*)d_in[11];
    const float* tw1 = (const float*)d_in[12];
    const float* tb1 = (const float*)d_in[13];
    const float* tw2 = (const float*)d_in[14];
    const float* tb2 = (const float*)d_in[15];
    float* out = (float*)d_out;

    float *p_b0, *p_b1, *p_feat, *p_R, *p_t0, *p_t1;
    cudaGetSymbolAddress((void**)&p_b0,   g_b0);
    cudaGetSymbolAddress((void**)&p_b1,   g_b1);
    cudaGetSymbolAddress((void**)&p_feat, g_feat);
    cudaGetSymbolAddress((void**)&p_R,    g_R);
    cudaGetSymbolAddress((void**)&p_t0,   g_t0);
    cudaGetSymbolAddress((void**)&p_t1,   g_t1);

    // embedding gather (independent of MLP chain)
    {
        int warps = N_TABLES * BATCH;
        int blocks = (warps + 7) / 8;
        embed_mean<<<blocks, 256>>>(tables, lS_i, p_feat);
    }

    // bottom MLP
    gemm_tf32<128><<<dim3(512 / 64, BATCH / 128), 256>>>(
        dense_x, 13, bw0, bb0, p_b0, 512, BATCH, 512, 13, 1);
    gemm_tf32<128><<<dim3(256 / 64, BATCH / 128), 256>>>(
        p_b0, 512, bw1, bb1, p_b1, 256, BATCH, 256, 512, 1);
    // bot2: N=64 -> BM=64 config for 128 CTAs
    gemm_tf32<64><<<dim3(1, BATCH / 64), 128>>>(
        p_b1, 256, bw2, bb2, p_feat, FEAT_LD, BATCH, 64, 256, 1);

    // interaction -> R
    interact<<<BATCH, 128>>>(p_feat, p_R);

    // top MLP
    gemm_tf32<128><<<dim3(512 / 64, BATCH / 128), 256>>>(
        p_R, RWIDTH, tw0, tb0, p_t0, 512, BATCH, 512, RWIDTH, 1);
    gemm_tf32<128><<<dim3(256 / 64, BATCH / 128), 256>>>(
        p_t0, 512, tw1, tb1, p_t1, 256, BATCH, 256, 512, 1);
    top_final<<<BATCH / 8, 256>>>(p_t1, tw2, tb2, out);
}

// round 4
// speedup vs baseline: 1.5428x; 1.5428x over previous
#include <cuda_runtime.h>
#include <math.h>
#include <stdint.h>

#define N_TABLES 26
#define ROWS 100001
#define D 64
#define BATCH 8192
#define L 4
#define NFEAT 27
#define FEAT_LD (NFEAT * D)  // 1728
#define NPAIR 351
#define RLD 416              // padded R stride (K for top0)

// ---------------- scratch (device globals) ----------------------------------
__device__ float g_b0[BATCH * 512];
__device__ float g_b1[BATCH * 256];
__device__ float g_feat[BATCH * FEAT_LD];
__device__ float g_R[BATCH * RLD];
__device__ float g_t0[BATCH * 512];
__device__ float g_t1[BATCH * 256];
// pre-rounded / padded inputs
__device__ float g_dx[BATCH * 32];      // dense_x padded 13->32
__device__ float g_w0[512 * 32];        // bw0 padded 13->32
__device__ float g_w1[256 * 512];
__device__ float g_w2[64 * 256];
__device__ float g_tw0[512 * RLD];      // tw0 padded 415->416
__device__ float g_tw1[256 * 512];

__device__ __forceinline__ float to_tf32(float v) {
    float r;
    asm("cvt.rna.tf32.f32 %0, %1;" : "=f"(r) : "f"(v));
    return r;
}

#define CP_ASYNC16(dst, src) \
    asm volatile("cp.async.cg.shared.global [%0], [%1], 16;\n" :: "r"(dst), "l"(src))
#define CP_COMMIT() asm volatile("cp.async.commit_group;\n")

// ---------------- prep: round weights / pad dense to tf32 --------------------
__global__ void __launch_bounds__(256)
prep(const float* __restrict__ dx, const float* __restrict__ bw0,
     const float* __restrict__ bw1, const float* __restrict__ bw2,
     const float* __restrict__ tw0, const float* __restrict__ tw1)
{
    int i = blockIdx.x * 256 + threadIdx.x;
    if (i < BATCH * 32) {
        int r = i >> 5, c = i & 31;
        g_dx[i] = (c < 13) ? to_tf32(dx[r * 13 + c]) : 0.f;
        return;
    }
    i -= BATCH * 32;
    if (i < 512 * 32) {
        int r = i >> 5, c = i & 31;
        g_w0[i] = (c < 13) ? to_tf32(bw0[r * 13 + c]) : 0.f;
        return;
    }
    i -= 512 * 32;
    if (i < 512 * RLD) {
        int r = i / RLD, c = i - r * RLD;
        g_tw0[i] = (c < 415) ? to_tf32(tw0[r * 415 + c]) : 0.f;
        return;
    }
    i -= 512 * RLD;
    if (i < 256 * 512) { g_w1[i] = to_tf32(bw1[i]); return; }
    i -= 256 * 512;
    if (i < 256 * 512) { g_tw1[i] = to_tf32(tw1[i]); return; }
    i -= 256 * 512;
    if (i < 64 * 256) { g_w2[i] = to_tf32(bw2[i]); return; }
}
#define PREP_TOTAL (BATCH*32 + 512*32 + 512*RLD + 256*512 + 256*512 + 64*256)

// ---------------- cp.async double-buffered tf32 GEMM -------------------------
// C[M,N] = act(A[M,K] * W[N,K]^T + bias); inputs already tf32-rounded.
// BM=BN=64, BK=32, 128 threads = 4 warps (2m x 2n), warp tile 32x32.
// Requires: K % 32 == 0, lda/ldw % 4 == 0 (16B-aligned rows).
#define SMS 2304  // 64*36 floats per buffer
template<int DO_RELU, int DO_ROUND>
__global__ void __launch_bounds__(128)
gemm_cp(const float* __restrict__ A, int lda,
        const float* __restrict__ W, int ldw,
        const float* __restrict__ bias,
        float* __restrict__ C, int ldc, int K)
{
    __shared__ float As[2][SMS];
    __shared__ float Bs[2][SMS];

    const int tid = threadIdx.x;
    const int warp = tid >> 5, lane = tid & 31;
    const int wm = warp >> 1, wn = warp & 1;
    const int g = lane >> 2, c = lane & 3;
    const int bm = blockIdx.y * 64, bn = blockIdx.x * 64;

    const float* Ab = A + (size_t)bm * lda;
    const float* Wb = W + (size_t)bn * ldw;

    const int r0 = tid >> 3;          // base row (0..15), rows r0+16i
    const int kc = (tid & 7) * 4;     // fixed 4-float column chunk

    const uint32_t sa = (uint32_t)__cvta_generic_to_shared(&As[0][0]);
    const uint32_t sb = (uint32_t)__cvta_generic_to_shared(&Bs[0][0]);

    float acc[2][4][4];
#pragma unroll
    for (int mt = 0; mt < 2; mt++)
#pragma unroll
        for (int nt = 0; nt < 4; nt++)
#pragma unroll
            for (int q = 0; q < 4; q++) acc[mt][nt][q] = 0.f;

    const int KT = K >> 5;

    // prologue: tile 0 -> buf 0
    {
        const float* ap = Ab + kc;
        const float* wp = Wb + kc;
        uint32_t da = sa + (uint32_t)(r0 * 36 + kc) * 4;
        uint32_t db = sb + (uint32_t)(r0 * 36 + kc) * 4;
#pragma unroll
        for (int i = 0; i < 4; i++) {
            CP_ASYNC16(da + i * (16 * 36 * 4), ap + (size_t)(r0 + 16 * i) * lda);
            CP_ASYNC16(db + i * (16 * 36 * 4), wp + (size_t)(r0 + 16 * i) * ldw);
        }
        CP_COMMIT();
    }

    for (int kt = 0; kt < KT; kt++) {
        const int cur = kt & 1;
        if (kt + 1 < KT) {
            const int nb = cur ^ 1;
            const float* ap = Ab + (size_t)(kt + 1) * 32 + kc;
            const float* wp = Wb + (size_t)(kt + 1) * 32 + kc;
            uint32_t da = sa + (uint32_t)(nb * SMS + r0 * 36 + kc) * 4;
            uint32_t db = sb + (uint32_t)(nb * SMS + r0 * 36 + kc) * 4;
#pragma unroll
            for (int i = 0; i < 4; i++) {
                CP_ASYNC16(da + i * (16 * 36 * 4), ap + (size_t)(r0 + 16 * i) * lda);
                CP_ASYNC16(db + i * (16 * 36 * 4), wp + (size_t)(r0 + 16 * i) * ldw);
            }
            CP_COMMIT();
            asm volatile("cp.async.wait_group 1;\n");
        } else {
            asm volatile("cp.async.wait_group 0;\n");
        }
        __syncthreads();

        const float* as = As[cur];
        const float* bs = Bs[cur];
#pragma unroll
        for (int ks = 0; ks < 4; ks++) {
            const int kk = ks * 8;
            uint32_t a[2][4], b[4][2];
#pragma unroll
            for (int mt = 0; mt < 2; mt++) {
                int mb = wm * 32 + mt * 16;
                a[mt][0] = __float_as_uint(as[(mb + g) * 36 + kk + c]);
                a[mt][1] = __float_as_uint(as[(mb + g + 8) * 36 + kk + c]);
                a[mt][2] = __float_as_uint(as[(mb + g) * 36 + kk + c + 4]);
                a[mt][3] = __float_as_uint(as[(mb + g + 8) * 36 + kk + c + 4]);
            }
#pragma unroll
            for (int nt = 0; nt < 4; nt++) {
                int nb2 = wn * 32 + nt * 8;
                b[nt][0] = __float_as_uint(bs[(nb2 + g) * 36 + kk + c]);
                b[nt][1] = __float_as_uint(bs[(nb2 + g) * 36 + kk + c + 4]);
            }
#pragma unroll
            for (int mt = 0; mt < 2; mt++)
#pragma unroll
                for (int nt = 0; nt < 4; nt++) {
                    asm volatile(
                        "mma.sync.aligned.m16n8k8.row.col.f32.tf32.tf32.f32 "
                        "{%0,%1,%2,%3}, {%4,%5,%6,%7}, {%8,%9}, {%0,%1,%2,%3};\n"
                        : "+f"(acc[mt][nt][0]), "+f"(acc[mt][nt][1]),
                          "+f"(acc[mt][nt][2]), "+f"(acc[mt][nt][3])
                        : "r"(a[mt][0]), "r"(a[mt][1]), "r"(a[mt][2]), "r"(a[mt][3]),
                          "r"(b[nt][0]), "r"(b[nt][1]));
                }
        }
        __syncthreads();
    }

    // epilogue
#pragma unroll
    for (int mt = 0; mt < 2; mt++) {
        int row0 = bm + wm * 32 + mt * 16 + g;
#pragma unroll
        for (int nt = 0; nt < 4; nt++) {
            int col = bn + wn * 32 + nt * 8 + c * 2;
            float b0 = bias[col], b1 = bias[col + 1];
            float v0 = acc[mt][nt][0] + b0;
            float v1 = acc[mt][nt][1] + b1;
            float v2 = acc[mt][nt][2] + b0;
            float v3 = acc[mt][nt][3] + b1;
            if (DO_RELU) {
                v0 = fmaxf(v0, 0.f); v1 = fmaxf(v1, 0.f);
                v2 = fmaxf(v2, 0.f); v3 = fmaxf(v3, 0.f);
            }
            if (DO_ROUND) {
                v0 = to_tf32(v0); v1 = to_tf32(v1);
                v2 = to_tf32(v2); v3 = to_tf32(v3);
            }
            *(float2*)&C[(size_t)row0 * ldc + col] = make_float2(v0, v1);
            *(float2*)&C[(size_t)(row0 + 8) * ldc + col] = make_float2(v2, v3);
        }
    }
}

// ---------------- embedding gather + mean over L=4 (tf32-rounded out) --------
__global__ void __launch_bounds__(256)
embed_mean(const float* __restrict__ tables, const int* __restrict__ lS_i,
           float* __restrict__ feat)
{
    int gw = (blockIdx.x * blockDim.x + threadIdx.x) >> 5;
    int lane = threadIdx.x & 31;
    if (gw >= N_TABLES * BATCH) return;
    int t = gw / BATCH;
    int b = gw - t * BATCH;

    const int* idx = lS_i + (size_t)t * BATCH * L + (size_t)b * L;
    const float* tab = tables + (size_t)t * ROWS * D;

    int i0 = idx[0], i1 = idx[1], i2 = idx[2], i3 = idx[3];
    float2 v0 = ((const float2*)(tab + (size_t)i0 * D))[lane];
    float2 v1 = ((const float2*)(tab + (size_t)i1 * D))[lane];
    float2 v2 = ((const float2*)(tab + (size_t)i2 * D))[lane];
    float2 v3 = ((const float2*)(tab + (size_t)i3 * D))[lane];

    float sx = (v0.x + v1.x) + (v2.x + v3.x);
    float sy = (v0.y + v1.y) + (v2.y + v3.y);
    float2* out = (float2*)(feat + (size_t)b * FEAT_LD + (size_t)(1 + t) * D);
    out[lane] = make_float2(to_tf32(sx * 0.25f), to_tf32(sy * 0.25f));
}

// ---------------- tensor-core interaction ------------------------------------
// One warp per sample: Z = T * T^T via m16n8k8 tf32 mma (32x32x64, rows>=27 junk),
// emit strict lower triangle into R[b][64..414]; copy x into R[b][0..63].
#define TS 68            // padded row stride (floats), 16B aligned
__global__ void __launch_bounds__(128)
interact_mma(const float* __restrict__ feat, float* __restrict__ R)
{
    __shared__ float Ts[4][32 * TS];
    const int warp = threadIdx.x >> 5;
    const int lane = threadIdx.x & 31;
    const int b = blockIdx.x * 4 + warp;
    const int g = lane >> 2, c = lane & 3;

    float* tw = Ts[warp];
    const float* f = feat + (size_t)b * FEAT_LD;
    // load 27x64 tile (432 float4 chunks)
    for (int q = lane; q < 432; q += 32) {
        int fi = q >> 4, kc = (q & 15) * 4;
        *(float4*)&tw[fi * TS + kc] = *(const float4*)&f[fi * D + kc];
    }
    __syncwarp();

    float acc[2][4][4];
#pragma unroll
    for (int mt = 0; mt < 2; mt++)
#pragma unroll
        for (int nt = 0; nt < 4; nt++)
#pragma unroll
            for (int q = 0; q < 4; q++) acc[mt][nt][q] = 0.f;

#pragma unroll
    for (int ks = 0; ks < 8; ks++) {
        const int kk = ks * 8;
        uint32_t a[2][4], bfr[4][2];
#pragma unroll
        for (int mt = 0; mt < 2; mt++) {
            int mb = mt * 16;
            a[mt][0] = __float_as_uint(tw[(mb + g) * TS + kk + c]);
            a[mt][1] = __float_as_uint(tw[(mb + g + 8) * TS + kk + c]);
            a[mt][2] = __float_as_uint(tw[(mb + g) * TS + kk + c + 4]);
            a[mt][3] = __float_as_uint(tw[(mb + g + 8) * TS + kk + c + 4]);
        }
#pragma unroll
        for (int nt = 0; nt < 4; nt++) {
            int nb = nt * 8;
            bfr[nt][0] = __float_as_uint(tw[(nb + g) * TS + kk + c]);
            bfr[nt][1] = __float_as_uint(tw[(nb + g) * TS + kk + c + 4]);
        }
#pragma unroll
        for (int mt = 0; mt < 2; mt++)
#pragma unroll
            for (int nt = 0; nt < 4; nt++) {
                asm volatile(
                    "mma.sync.aligned.m16n8k8.row.col.f32.tf32.tf32.f32 "
                    "{%0,%1,%2,%3}, {%4,%5,%6,%7}, {%8,%9}, {%0,%1,%2,%3};\n"
                    : "+f"(acc[mt][nt][0]), "+f"(acc[mt][nt][1]),
                      "+f"(acc[mt][nt][2]), "+f"(acc[mt][nt][3])
                    : "r"(a[mt][0]), "r"(a[mt][1]), "r"(a[mt][2]), "r"(a[mt][3]),
                      "r"(bfr[nt][0]), "r"(bfr[nt][1]));
            }
    }

    float* r = R + (size_t)b * RLD;
    // copy dense feature x (row 0 of T, already tf32-rounded)
    for (int k = lane; k < D; k += 32) r[k] = tw[k];
    if (lane == 0) r[415] = 0.f;   // zero pad column

    // scatter strict-lower-triangle entries
#pragma unroll
    for (int mt = 0; mt < 2; mt++) {
        int row0 = mt * 16 + g;
#pragma unroll
        for (int nt = 0; nt < 4; nt++) {
            int col = nt * 8 + c * 2;
#pragma unroll
            for (int q = 0; q < 4; q++) {
                int ri = row0 + ((q >> 1) << 3);
                int cj = col + (q & 1);
                if (cj < ri && ri < NFEAT)
                    r[64 + ri * (ri - 1) / 2 + cj] = to_tf32(acc[mt][nt][q]);
            }
        }
    }
}

// ---------------- final layer: [8192,256] x [256] + b ------------------------
__global__ void __launch_bounds__(256)
top_final(const float* __restrict__ A, const float* __restrict__ w,
          const float* __restrict__ bias, float* __restrict__ out)
{
    __shared__ float ws[256];
    int tid = threadIdx.x;
    ws[tid] = w[tid];
    __syncthreads();

    int warp = tid >> 5, lane = tid & 31;
    int row = blockIdx.x * 8 + warp;
    const float* a = A + (size_t)row * 256;
    float s = 0.f;
#pragma unroll
    for (int k = 0; k < 8; k++) s += a[lane + k * 32] * ws[lane + k * 32];
#pragma unroll
    for (int o = 16; o > 0; o >>= 1) s += __shfl_xor_sync(0xffffffffu, s, o);
    if (lane == 0) out[row] = s + bias[0];
}

// ---------------- launch ------------------------------------------------------
extern "C" void kernel_launch(void* const* d_in, const int* in_sizes, int n_in,
                              void* d_out, int out_size)
{
    const float* dense_x = (const float*)d_in[0];
    const int*   lS_i    = (const int*)d_in[2];
    const float* tables  = (const float*)d_in[3];
    const float* bw0 = (const float*)d_in[4];
    const float* bb0 = (const float*)d_in[5];
    const float* bw1 = (const float*)d_in[6];
    const float* bb1 = (const float*)d_in[7];
    const float* bw2 = (const float*)d_in[8];
    const float* bb2 = (const float*)d_in[9];
    const float* tw0 = (const float*)d_in[10];
    const float* tb0 = (const float*)d_in[11];
    const float* tw1 = (const float*)d_in[12];
    const float* tb1 = (const float*)d_in[13];
    const float* tw2 = (const float*)d_in[14];
    const float* tb2 = (const float*)d_in[15];
    float* out = (float*)d_out;

    float *p_b0, *p_b1, *p_feat, *p_R, *p_t0, *p_t1;
    float *p_dx, *p_w0, *p_w1, *p_w2, *p_tw0, *p_tw1;
    cudaGetSymbolAddress((void**)&p_b0,   g_b0);
    cudaGetSymbolAddress((void**)&p_b1,   g_b1);
    cudaGetSymbolAddress((void**)&p_feat, g_feat);
    cudaGetSymbolAddress((void**)&p_R,    g_R);
    cudaGetSymbolAddress((void**)&p_t0,   g_t0);
    cudaGetSymbolAddress((void**)&p_t1,   g_t1);
    cudaGetSymbolAddress((void**)&p_dx,   g_dx);
    cudaGetSymbolAddress((void**)&p_w0,   g_w0);
    cudaGetSymbolAddress((void**)&p_w1,   g_w1);
    cudaGetSymbolAddress((void**)&p_w2,   g_w2);
    cudaGetSymbolAddress((void**)&p_tw0,  g_tw0);
    cudaGetSymbolAddress((void**)&p_tw1,  g_tw1);

    // prep: tf32-round + pad weights and dense input
    prep<<<(PREP_TOTAL + 255) / 256, 256>>>(dense_x, bw0, bw1, bw2, tw0, tw1);

    // embedding gather (independent)
    {
        int warps = N_TABLES * BATCH;
        embed_mean<<<(warps + 7) / 8, 256>>>(tables, lS_i, p_feat);
    }

    // bottom MLP
    gemm_cp<1, 1><<<dim3(8, 128), 128>>>(p_dx, 32, p_w0, 32, bb0, p_b0, 512, 32);
    gemm_cp<1, 1><<<dim3(4, 128), 128>>>(p_b0, 512, p_w1, 512, bb1, p_b1, 256, 512);
    gemm_cp<1, 1><<<dim3(1, 128), 128>>>(p_b1, 256, p_w2, 256, bb2, p_feat, FEAT_LD, 256);

    // interaction -> R (stride 416)
    interact_mma<<<BATCH / 4, 128>>>(p_feat, p_R);

    // top MLP
    gemm_cp<1, 1><<<dim3(8, 128), 128>>>(p_R, RLD, p_tw0, RLD, tb0, p_t0, 512, RLD);
    gemm_cp<1, 0><<<dim3(4, 128), 128>>>(p_t0, 512, p_tw1, 512, tb1, p_t1, 256, 512);
    top_final<<<BATCH / 8, 256>>>(p_t1, tw2, tb2, out);
}

// round 5
// speedup vs baseline: 1.5672x; 1.0158x over previous
#include <cuda_runtime.h>
#include <math.h>
#include <stdint.h>

#define N_TABLES 26
#define ROWS 100001
#define D 64
#define BATCH 8192
#define L 4
#define NFEAT 27
#define FEAT_LD (NFEAT * D)  // 1728
#define NPAIR 351
#define RLD 416              // padded R stride (K for top0)

// ---------------- scratch (device globals) ----------------------------------
__device__ float g_b0[BATCH * 512];
__device__ float g_b1[BATCH * 256];
__device__ float g_feat[BATCH * FEAT_LD];
__device__ float g_R[BATCH * RLD];
__device__ float g_t0[BATCH * 512];
__device__ float g_t1[BATCH * 256];
// pre-rounded / padded inputs
__device__ float g_dx[BATCH * 32];
__device__ float g_w0[512 * 32];
__device__ float g_w1[256 * 512];
__device__ float g_w2[64 * 256];
__device__ float g_tw0[512 * RLD];
__device__ float g_tw1[256 * 512];

__device__ __forceinline__ float to_tf32(float v) {
    float r;
    asm("cvt.rna.tf32.f32 %0, %1;" : "=f"(r) : "f"(v));
    return r;
}

#define CP_ASYNC16(dst, src) \
    asm volatile("cp.async.cg.shared.global [%0], [%1], 16;\n" :: "r"(dst), "l"(src))
#define CP_COMMIT() asm volatile("cp.async.commit_group;\n")
#define CP_WAIT(n)  asm volatile("cp.async.wait_group %0;\n" :: "n"(n))

#define MMA_TF32(acc, a0, a1, a2, a3, b0, b1)                                  \
    asm volatile(                                                              \
        "mma.sync.aligned.m16n8k8.row.col.f32.tf32.tf32.f32 "                  \
        "{%0,%1,%2,%3}, {%4,%5,%6,%7}, {%8,%9}, {%0,%1,%2,%3};\n"              \
        : "+f"(acc[0]), "+f"(acc[1]), "+f"(acc[2]), "+f"(acc[3])               \
        : "r"(a0), "r"(a1), "r"(a2), "r"(a3), "r"(b0), "r"(b1))

// ---------------- prep: round weights / pad dense to tf32 --------------------
__global__ void __launch_bounds__(256)
prep(const float* __restrict__ dx, const float* __restrict__ bw0,
     const float* __restrict__ bw1, const float* __restrict__ bw2,
     const float* __restrict__ tw0, const float* __restrict__ tw1)
{
    int i = blockIdx.x * 256 + threadIdx.x;
    if (i < BATCH * 32) {
        int r = i >> 5, c = i & 31;
        g_dx[i] = (c < 13) ? to_tf32(dx[r * 13 + c]) : 0.f;
        return;
    }
    i -= BATCH * 32;
    if (i < 512 * 32) {
        int r = i >> 5, c = i & 31;
        g_w0[i] = (c < 13) ? to_tf32(bw0[r * 13 + c]) : 0.f;
        return;
    }
    i -= 512 * 32;
    if (i < 512 * RLD) {
        int r = i / RLD, c = i - r * RLD;
        g_tw0[i] = (c < 415) ? to_tf32(tw0[r * 415 + c]) : 0.f;
        return;
    }
    i -= 512 * RLD;
    if (i < 256 * 512) { g_w1[i] = to_tf32(bw1[i]); return; }
    i -= 256 * 512;
    if (i < 256 * 512) { g_tw1[i] = to_tf32(tw1[i]); return; }
    i -= 256 * 512;
    if (i < 64 * 256) { g_w2[i] = to_tf32(bw2[i]); return; }
}
#define PREP_TOTAL (BATCH*32 + 512*32 + 512*RLD + 256*512 + 256*512 + 64*256)

// ---------------- R4 cp.async GEMM (BM=64) — used for bot0, bot2 -------------
#define SMS 2304  // 64*36 floats per buffer
template<int DO_RELU, int DO_ROUND>
__global__ void __launch_bounds__(128)
gemm_cp(const float* __restrict__ A, int lda,
        const float* __restrict__ W, int ldw,
        const float* __restrict__ bias,
        float* __restrict__ C, int ldc, int K)
{
    __shared__ float As[2][SMS];
    __shared__ float Bs[2][SMS];

    const int tid = threadIdx.x;
    const int warp = tid >> 5, lane = tid & 31;
    const int wm = warp >> 1, wn = warp & 1;
    const int g = lane >> 2, c = lane & 3;
    const int bm = blockIdx.y * 64, bn = blockIdx.x * 64;

    const float* Ab = A + (size_t)bm * lda;
    const float* Wb = W + (size_t)bn * ldw;

    const int r0 = tid >> 3;
    const int kc = (tid & 7) * 4;

    const uint32_t sa = (uint32_t)__cvta_generic_to_shared(&As[0][0]);
    const uint32_t sb = (uint32_t)__cvta_generic_to_shared(&Bs[0][0]);

    float acc[2][4][4];
#pragma unroll
    for (int mt = 0; mt < 2; mt++)
#pragma unroll
        for (int nt = 0; nt < 4; nt++)
#pragma unroll
            for (int q = 0; q < 4; q++) acc[mt][nt][q] = 0.f;

    const int KT = K >> 5;

    {
        const float* ap = Ab + kc;
        const float* wp = Wb + kc;
        uint32_t da = sa + (uint32_t)(r0 * 36 + kc) * 4;
        uint32_t db = sb + (uint32_t)(r0 * 36 + kc) * 4;
#pragma unroll
        for (int i = 0; i < 4; i++) {
            CP_ASYNC16(da + i * (16 * 36 * 4), ap + (size_t)(r0 + 16 * i) * lda);
            CP_ASYNC16(db + i * (16 * 36 * 4), wp + (size_t)(r0 + 16 * i) * ldw);
        }
        CP_COMMIT();
    }

    for (int kt = 0; kt < KT; kt++) {
        const int cur = kt & 1;
        if (kt + 1 < KT) {
            const int nb = cur ^ 1;
            const float* ap = Ab + (size_t)(kt + 1) * 32 + kc;
            const float* wp = Wb + (size_t)(kt + 1) * 32 + kc;
            uint32_t da = sa + (uint32_t)(nb * SMS + r0 * 36 + kc) * 4;
            uint32_t db = sb + (uint32_t)(nb * SMS + r0 * 36 + kc) * 4;
#pragma unroll
            for (int i = 0; i < 4; i++) {
                CP_ASYNC16(da + i * (16 * 36 * 4), ap + (size_t)(r0 + 16 * i) * lda);
                CP_ASYNC16(db + i * (16 * 36 * 4), wp + (size_t)(r0 + 16 * i) * ldw);
            }
            CP_COMMIT();
            CP_WAIT(1);
        } else {
            CP_WAIT(0);
        }
        __syncthreads();

        const float* as = As[cur];
        const float* bs = Bs[cur];
#pragma unroll
        for (int ks = 0; ks < 4; ks++) {
            const int kk = ks * 8;
            uint32_t a[2][4], b[4][2];
#pragma unroll
            for (int mt = 0; mt < 2; mt++) {
                int mb = wm * 32 + mt * 16;
                a[mt][0] = __float_as_uint(as[(mb + g) * 36 + kk + c]);
                a[mt][1] = __float_as_uint(as[(mb + g + 8) * 36 + kk + c]);
                a[mt][2] = __float_as_uint(as[(mb + g) * 36 + kk + c + 4]);
                a[mt][3] = __float_as_uint(as[(mb + g + 8) * 36 + kk + c + 4]);
            }
#pragma unroll
            for (int nt = 0; nt < 4; nt++) {
                int nb2 = wn * 32 + nt * 8;
                b[nt][0] = __float_as_uint(bs[(nb2 + g) * 36 + kk + c]);
                b[nt][1] = __float_as_uint(bs[(nb2 + g) * 36 + kk + c + 4]);
            }
#pragma unroll
            for (int mt = 0; mt < 2; mt++)
#pragma unroll
                for (int nt = 0; nt < 4; nt++)
                    MMA_TF32(acc[mt][nt], a[mt][0], a[mt][1], a[mt][2], a[mt][3],
                             b[nt][0], b[nt][1]);
        }
        __syncthreads();
    }

#pragma unroll
    for (int mt = 0; mt < 2; mt++) {
        int row0 = bm + wm * 32 + mt * 16 + g;
#pragma unroll
        for (int nt = 0; nt < 4; nt++) {
            int col = bn + wn * 32 + nt * 8 + c * 2;
            float b0 = bias[col], b1 = bias[col + 1];
            float v0 = acc[mt][nt][0] + b0;
            float v1 = acc[mt][nt][1] + b1;
            float v2 = acc[mt][nt][2] + b0;
            float v3 = acc[mt][nt][3] + b1;
            if (DO_RELU) {
                v0 = fmaxf(v0, 0.f); v1 = fmaxf(v1, 0.f);
                v2 = fmaxf(v2, 0.f); v3 = fmaxf(v3, 0.f);
            }
            if (DO_ROUND) {
                v0 = to_tf32(v0); v1 = to_tf32(v1);
                v2 = to_tf32(v2); v3 = to_tf32(v3);
            }
            *(float2*)&C[(size_t)row0 * ldc + col] = make_float2(v0, v1);
            *(float2*)&C[(size_t)(row0 + 8) * ldc + col] = make_float2(v2, v3);
        }
    }
}

// ---------------- 3-stage m64n32-warp-tile GEMM (BM=128, BN=64) --------------
// 128 threads = 4 warps: wm in {0,1} (64 rows each), wn in {0,1} (32 cols each).
// Dynamic smem: 3 stages x 192 rows x 36 floats. One __syncthreads per K-iter.
#define ST3 6912   // floats per stage (192*36)
template<int DO_RELU, int DO_ROUND>
__global__ void __launch_bounds__(128)
gemm3(const float* __restrict__ A, int lda,
      const float* __restrict__ W, int ldw,
      const float* __restrict__ bias,
      float* __restrict__ C, int ldc, int K)
{
    extern __shared__ float sm3[];

    const int tid = threadIdx.x;
    const int warp = tid >> 5, lane = tid & 31;
    const int wm = warp >> 1, wn = warp & 1;
    const int g = lane >> 2, c = lane & 3;
    const int bm = blockIdx.y * 128, bn = blockIdx.x * 64;

    const float* Ab = A + (size_t)bm * lda;
    const float* Wb = W + (size_t)bn * ldw;
    const uint32_t sbase = (uint32_t)__cvta_generic_to_shared(sm3);

    float acc[4][4][4];
#pragma unroll
    for (int mt = 0; mt < 4; mt++)
#pragma unroll
        for (int nt = 0; nt < 4; nt++)
#pragma unroll
            for (int q = 0; q < 4; q++) acc[mt][nt][q] = 0.f;

    const int KT = K >> 5;

    // tile issue: 192 rows x 32 floats = 1536 float4 chunks, 12 per thread
    auto issue = [&](int kt, int stage) {
        const int off = kt * 32;
        const uint32_t sb = sbase + (uint32_t)stage * (ST3 * 4);
#pragma unroll
        for (int i = 0; i < 12; i++) {
            int q = i * 128 + tid;
            int row = q >> 3, kc = (q & 7) * 4;
            const float* src = (row < 128)
                ? Ab + (size_t)row * lda + off + kc
                : Wb + (size_t)(row - 128) * ldw + off + kc;
            CP_ASYNC16(sb + (uint32_t)(row * 36 + kc) * 4, src);
        }
        CP_COMMIT();
    };

    issue(0, 0);
    if (KT > 1) issue(1, 1);

    for (int kt = 0; kt < KT; kt++) {
        if (kt + 1 < KT) { CP_WAIT(1); } else { CP_WAIT(0); }
        __syncthreads();
        if (kt + 2 < KT) issue(kt + 2, (kt + 2) % 3);

        const float* st = sm3 + (size_t)(kt % 3) * ST3;
        const float* as = st;                    // A rows 0..127
        const float* bs = st + 128 * 36;         // B rows 0..63
#pragma unroll
        for (int ks = 0; ks < 4; ks++) {
            const int kk = ks * 8;
            uint32_t a[4][4], b[4][2];
#pragma unroll
            for (int mt = 0; mt < 4; mt++) {
                int mb = wm * 64 + mt * 16;
                a[mt][0] = __float_as_uint(as[(mb + g) * 36 + kk + c]);
                a[mt][1] = __float_as_uint(as[(mb + g + 8) * 36 + kk + c]);
                a[mt][2] = __float_as_uint(as[(mb + g) * 36 + kk + c + 4]);
                a[mt][3] = __float_as_uint(as[(mb + g + 8) * 36 + kk + c + 4]);
            }
#pragma unroll
            for (int nt = 0; nt < 4; nt++) {
                int nb = wn * 32 + nt * 8;
                b[nt][0] = __float_as_uint(bs[(nb + g) * 36 + kk + c]);
                b[nt][1] = __float_as_uint(bs[(nb + g) * 36 + kk + c + 4]);
            }
#pragma unroll
            for (int mt = 0; mt < 4; mt++)
#pragma unroll
                for (int nt = 0; nt < 4; nt++)
                    MMA_TF32(acc[mt][nt], a[mt][0], a[mt][1], a[mt][2], a[mt][3],
                             b[nt][0], b[nt][1]);
        }
    }

#pragma unroll
    for (int mt = 0; mt < 4; mt++) {
        int row0 = bm + wm * 64 + mt * 16 + g;
#pragma unroll
        for (int nt = 0; nt < 4; nt++) {
            int col = bn + wn * 32 + nt * 8 + c * 2;
            float b0 = bias[col], b1 = bias[col + 1];
            float v0 = acc[mt][nt][0] + b0;
            float v1 = acc[mt][nt][1] + b1;
            float v2 = acc[mt][nt][2] + b0;
            float v3 = acc[mt][nt][3] + b1;
            if (DO_RELU) {
                v0 = fmaxf(v0, 0.f); v1 = fmaxf(v1, 0.f);
                v2 = fmaxf(v2, 0.f); v3 = fmaxf(v3, 0.f);
            }
            if (DO_ROUND) {
                v0 = to_tf32(v0); v1 = to_tf32(v1);
                v2 = to_tf32(v2); v3 = to_tf32(v3);
            }
            *(float2*)&C[(size_t)row0 * ldc + col] = make_float2(v0, v1);
            *(float2*)&C[(size_t)(row0 + 8) * ldc + col] = make_float2(v2, v3);
        }
    }
}
#define SM3_BYTES (3 * ST3 * 4)

// ---------------- embedding gather + mean over L=4 ---------------------------
__global__ void __launch_bounds__(256)
embed_mean(const float* __restrict__ tables, const int* __restrict__ lS_i,
           float* __restrict__ feat)
{
    int gw = (blockIdx.x * blockDim.x + threadIdx.x) >> 5;
    int lane = threadIdx.x & 31;
    if (gw >= N_TABLES * BATCH) return;
    int t = gw / BATCH;
    int b = gw - t * BATCH;

    const int* idx = lS_i + (size_t)t * BATCH * L + (size_t)b * L;
    const float* tab = tables + (size_t)t * ROWS * D;

    int i0 = idx[0], i1 = idx[1], i2 = idx[2], i3 = idx[3];
    float2 v0 = ((const float2*)(tab + (size_t)i0 * D))[lane];
    float2 v1 = ((const float2*)(tab + (size_t)i1 * D))[lane];
    float2 v2 = ((const float2*)(tab + (size_t)i2 * D))[lane];
    float2 v3 = ((const float2*)(tab + (size_t)i3 * D))[lane];

    float sx = (v0.x + v1.x) + (v2.x + v3.x);
    float sy = (v0.y + v1.y) + (v2.y + v3.y);
    float2* out = (float2*)(feat + (size_t)b * FEAT_LD + (size_t)(1 + t) * D);
    out[lane] = make_float2(to_tf32(sx * 0.25f), to_tf32(sy * 0.25f));
}

// ---------------- tensor-core interaction ------------------------------------
#define TS 68
__global__ void __launch_bounds__(128)
interact_mma(const float* __restrict__ feat, float* __restrict__ R)
{
    __shared__ float Ts[4][32 * TS];
    const int warp = threadIdx.x >> 5;
    const int lane = threadIdx.x & 31;
    const int b = blockIdx.x * 4 + warp;
    const int g = lane >> 2, c = lane & 3;

    float* tw = Ts[warp];
    const float* f = feat + (size_t)b * FEAT_LD;
    for (int q = lane; q < 432; q += 32) {
        int fi = q >> 4, kc = (q & 15) * 4;
        *(float4*)&tw[fi * TS + kc] = *(const float4*)&f[fi * D + kc];
    }
    __syncwarp();

    float acc[2][4][4];
#pragma unroll
    for (int mt = 0; mt < 2; mt++)
#pragma unroll
        for (int nt = 0; nt < 4; nt++)
#pragma unroll
            for (int q = 0; q < 4; q++) acc[mt][nt][q] = 0.f;

#pragma unroll
    for (int ks = 0; ks < 8; ks++) {
        const int kk = ks * 8;
        uint32_t a[2][4], bfr[4][2];
#pragma unroll
        for (int mt = 0; mt < 2; mt++) {
            int mb = mt * 16;
            a[mt][0] = __float_as_uint(tw[(mb + g) * TS + kk + c]);
            a[mt][1] = __float_as_uint(tw[(mb + g + 8) * TS + kk + c]);
            a[mt][2] = __float_as_uint(tw[(mb + g) * TS + kk + c + 4]);
            a[mt][3] = __float_as_uint(tw[(mb + g + 8) * TS + kk + c + 4]);
        }
#pragma unroll
        for (int nt = 0; nt < 4; nt++) {
            int nb = nt * 8;
            bfr[nt][0] = __float_as_uint(tw[(nb + g) * TS + kk + c]);
            bfr[nt][1] = __float_as_uint(tw[(nb + g) * TS + kk + c + 4]);
        }
#pragma unroll
        for (int mt = 0; mt < 2; mt++)
#pragma unroll
            for (int nt = 0; nt < 4; nt++)
                MMA_TF32(acc[mt][nt], a[mt][0], a[mt][1], a[mt][2], a[mt][3],
                         bfr[nt][0], bfr[nt][1]);
    }

    float* r = R + (size_t)b * RLD;
    for (int k = lane; k < D; k += 32) r[k] = tw[k];
    if (lane == 0) r[415] = 0.f;

#pragma unroll
    for (int mt = 0; mt < 2; mt++) {
        int row0 = mt * 16 + g;
#pragma unroll
        for (int nt = 0; nt < 4; nt++) {
            int col = nt * 8 + c * 2;
#pragma unroll
            for (int q = 0; q < 4; q++) {
                int ri = row0 + ((q >> 1) << 3);
                int cj = col + (q & 1);
                if (cj < ri && ri < NFEAT)
                    r[64 + ri * (ri - 1) / 2 + cj] = to_tf32(acc[mt][nt][q]);
            }
        }
    }
}

// ---------------- final layer ------------------------------------------------
__global__ void __launch_bounds__(256)
top_final(const float* __restrict__ A, const float* __restrict__ w,
          const float* __restrict__ bias, float* __restrict__ out)
{
    __shared__ float ws[256];
    int tid = threadIdx.x;
    ws[tid] = w[tid];
    __syncthreads();

    int warp = tid >> 5, lane = tid & 31;
    int row = blockIdx.x * 8 + warp;
    const float* a = A + (size_t)row * 256;
    float s = 0.f;
#pragma unroll
    for (int k = 0; k < 8; k++) s += a[lane + k * 32] * ws[lane + k * 32];
#pragma unroll
    for (int o = 16; o > 0; o >>= 1) s += __shfl_xor_sync(0xffffffffu, s, o);
    if (lane == 0) out[row] = s + bias[0];
}

// ---------------- launch ------------------------------------------------------
extern "C" void kernel_launch(void* const* d_in, const int* in_sizes, int n_in,
                              void* d_out, int out_size)
{
    const float* dense_x = (const float*)d_in[0];
    const int*   lS_i    = (const int*)d_in[2];
    const float* tables  = (const float*)d_in[3];
    const float* bw0 = (const float*)d_in[4];
    const float* bb0 = (const float*)d_in[5];
    const float* bw1 = (const float*)d_in[6];
    const float* bb1 = (const float*)d_in[7];
    const float* bw2 = (const float*)d_in[8];
    const float* bb2 = (const float*)d_in[9];
    const float* tw0 = (const float*)d_in[10];
    const float* tb0 = (const float*)d_in[11];
    const float* tw1 = (const float*)d_in[12];
    const float* tb1 = (const float*)d_in[13];
    const float* tw2 = (const float*)d_in[14];
    const float* tb2 = (const float*)d_in[15];
    float* out = (float*)d_out;

    float *p_b0, *p_b1, *p_feat, *p_R, *p_t0, *p_t1;
    float *p_dx, *p_w0, *p_w1, *p_w2, *p_tw0, *p_tw1;
    cudaGetSymbolAddress((void**)&p_b0,   g_b0);
    cudaGetSymbolAddress((void**)&p_b1,   g_b1);
    cudaGetSymbolAddress((void**)&p_feat, g_feat);
    cudaGetSymbolAddress((void**)&p_R,    g_R);
    cudaGetSymbolAddress((void**)&p_t0,   g_t0);
    cudaGetSymbolAddress((void**)&p_t1,   g_t1);
    cudaGetSymbolAddress((void**)&p_dx,   g_dx);
    cudaGetSymbolAddress((void**)&p_w0,   g_w0);
    cudaGetSymbolAddress((void**)&p_w1,   g_w1);
    cudaGetSymbolAddress((void**)&p_w2,   g_w2);
    cudaGetSymbolAddress((void**)&p_tw0,  g_tw0);
    cudaGetSymbolAddress((void**)&p_tw1,  g_tw1);

    cudaFuncSetAttribute(gemm3<1, 1>,
        cudaFuncAttributeMaxDynamicSharedMemorySize, SM3_BYTES);
    cudaFuncSetAttribute(gemm3<1, 0>,
        cudaFuncAttributeMaxDynamicSharedMemorySize, SM3_BYTES);

    // fork: embed on side stream, MLP prep+bottom on main stream
    cudaStream_t s2;
    cudaStreamCreateWithFlags(&s2, cudaStreamNonBlocking);
    cudaEvent_t e0, e1;
    cudaEventCreateWithFlags(&e0, cudaEventDisableTiming);
    cudaEventCreateWithFlags(&e1, cudaEventDisableTiming);

    cudaEventRecord(e0, 0);
    cudaStreamWaitEvent(s2, e0, 0);
    {
        int warps = N_TABLES * BATCH;
        embed_mean<<<(warps + 7) / 8, 256, 0, s2>>>(tables, lS_i, p_feat);
    }
    cudaEventRecord(e1, s2);

    // main stream: prep + bottom MLP
    prep<<<(PREP_TOTAL + 255) / 256, 256>>>(dense_x, bw0, bw1, bw2, tw0, tw1);
    gemm_cp<1, 1><<<dim3(8, 128), 128>>>(p_dx, 32, p_w0, 32, bb0, p_b0, 512, 32);
    gemm3<1, 1><<<dim3(4, 64), 128, SM3_BYTES>>>(p_b0, 512, p_w1, 512, bb1, p_b1, 256, 512);
    gemm_cp<1, 1><<<dim3(1, 128), 128>>>(p_b1, 256, p_w2, 256, bb2, p_feat, FEAT_LD, 256);

    // join embed branch
    cudaStreamWaitEvent(0, e1, 0);

    // interaction -> R (stride 416)
    interact_mma<<<BATCH / 4, 128>>>(p_feat, p_R);

    // top MLP
    gemm3<1, 1><<<dim3(8, 64), 128, SM3_BYTES>>>(p_R, RLD, p_tw0, RLD, tb0, p_t0, 512, RLD);
    gemm3<1, 0><<<dim3(4, 64), 128, SM3_BYTES>>>(p_t0, 512, p_tw1, 512, tb1, p_t1, 256, 512);
    top_final<<<BATCH / 8, 256>>>(p_t1, tw2, tb2, out);
}

// round 6
// speedup vs baseline: 1.7291x; 1.1034x over previous
#include <cuda_runtime.h>
#include <math.h>
#include <stdint.h>

#define N_TABLES 26
#define ROWS 100001
#define D 64
#define BATCH 8192
#define L 4
#define NFEAT 27
#define FEAT_LD (NFEAT * D)  // 1728
#define NPAIR 351
#define RLD 416              // padded R stride (K for top0)

// ---------------- scratch (device globals) ----------------------------------
__device__ float g_b0[BATCH * 512];
__device__ float g_b1[BATCH * 256];
__device__ float g_feat[BATCH * FEAT_LD];
__device__ float g_R[BATCH * RLD];
__device__ float g_t0[BATCH * 512];
__device__ float g_t1[BATCH * 256];
// pre-rounded / padded inputs
__device__ float g_dx[BATCH * 32];
__device__ float g_w0[512 * 32];
__device__ float g_w1[256 * 512];
__device__ float g_w2[64 * 256];
__device__ float g_tw0[512 * RLD];
__device__ float g_tw1[256 * 512];

__device__ __forceinline__ float to_tf32(float v) {
    float r;
    asm("cvt.rna.tf32.f32 %0, %1;" : "=f"(r) : "f"(v));
    return r;
}

#define CP_ASYNC16(dst, src) \
    asm volatile("cp.async.cg.shared.global [%0], [%1], 16;\n" :: "r"(dst), "l"(src))
#define CP_COMMIT() asm volatile("cp.async.commit_group;\n")
#define CP_WAIT(n)  asm volatile("cp.async.wait_group %0;\n" :: "n"(n))

#define MMA_TF32(acc, a0, a1, a2, a3, b0, b1)                                  \
    asm volatile(                                                              \
        "mma.sync.aligned.m16n8k8.row.col.f32.tf32.tf32.f32 "                  \
        "{%0,%1,%2,%3}, {%4,%5,%6,%7}, {%8,%9}, {%0,%1,%2,%3};\n"              \
        : "+f"(acc[0]), "+f"(acc[1]), "+f"(acc[2]), "+f"(acc[3])               \
        : "r"(a0), "r"(a1), "r"(a2), "r"(a3), "r"(b0), "r"(b1))

// ---------------- prep: round weights / pad dense to tf32 --------------------
__global__ void __launch_bounds__(256)
prep(const float* __restrict__ dx, const float* __restrict__ bw0,
     const float* __restrict__ bw1, const float* __restrict__ bw2,
     const float* __restrict__ tw0, const float* __restrict__ tw1)
{
    int i = blockIdx.x * 256 + threadIdx.x;
    if (i < BATCH * 32) {
        int r = i >> 5, c = i & 31;
        g_dx[i] = (c < 13) ? to_tf32(dx[r * 13 + c]) : 0.f;
        return;
    }
    i -= BATCH * 32;
    if (i < 512 * 32) {
        int r = i >> 5, c = i & 31;
        g_w0[i] = (c < 13) ? to_tf32(bw0[r * 13 + c]) : 0.f;
        return;
    }
    i -= 512 * 32;
    if (i < 512 * RLD) {
        int r = i / RLD, c = i - r * RLD;
        g_tw0[i] = (c < 415) ? to_tf32(tw0[r * 415 + c]) : 0.f;
        return;
    }
    i -= 512 * RLD;
    if (i < 256 * 512) { g_w1[i] = to_tf32(bw1[i]); return; }
    i -= 256 * 512;
    if (i < 256 * 512) { g_tw1[i] = to_tf32(tw1[i]); return; }
    i -= 256 * 512;
    if (i < 64 * 256) { g_w2[i] = to_tf32(bw2[i]); return; }
}
#define PREP_TOTAL (BATCH*32 + 512*32 + 512*RLD + 256*512 + 256*512 + 64*256)

// ---------------- R4 cp.async GEMM (BM=64) — bot0, bot2 ----------------------
#define SMS 2304  // 64*36 floats per buffer
template<int DO_RELU, int DO_ROUND>
__global__ void __launch_bounds__(128)
gemm_cp(const float* __restrict__ A, int lda,
        const float* __restrict__ W, int ldw,
        const float* __restrict__ bias,
        float* __restrict__ C, int ldc, int K)
{
    __shared__ float As[2][SMS];
    __shared__ float Bs[2][SMS];

    const int tid = threadIdx.x;
    const int warp = tid >> 5, lane = tid & 31;
    const int wm = warp >> 1, wn = warp & 1;
    const int g = lane >> 2, c = lane & 3;
    const int bm = blockIdx.y * 64, bn = blockIdx.x * 64;

    const float* Ab = A + (size_t)bm * lda;
    const float* Wb = W + (size_t)bn * ldw;

    const int r0 = tid >> 3;
    const int kc = (tid & 7) * 4;

    const uint32_t sa = (uint32_t)__cvta_generic_to_shared(&As[0][0]);
    const uint32_t sb = (uint32_t)__cvta_generic_to_shared(&Bs[0][0]);

    float acc[2][4][4];
#pragma unroll
    for (int mt = 0; mt < 2; mt++)
#pragma unroll
        for (int nt = 0; nt < 4; nt++)
#pragma unroll
            for (int q = 0; q < 4; q++) acc[mt][nt][q] = 0.f;

    const int KT = K >> 5;

    {
        const float* ap = Ab + kc;
        const float* wp = Wb + kc;
        uint32_t da = sa + (uint32_t)(r0 * 36 + kc) * 4;
        uint32_t db = sb + (uint32_t)(r0 * 36 + kc) * 4;
#pragma unroll
        for (int i = 0; i < 4; i++) {
            CP_ASYNC16(da + i * (16 * 36 * 4), ap + (size_t)(r0 + 16 * i) * lda);
            CP_ASYNC16(db + i * (16 * 36 * 4), wp + (size_t)(r0 + 16 * i) * ldw);
        }
        CP_COMMIT();
    }

    for (int kt = 0; kt < KT; kt++) {
        const int cur = kt & 1;
        if (kt + 1 < KT) {
            const int nb = cur ^ 1;
            const float* ap = Ab + (size_t)(kt + 1) * 32 + kc;
            const float* wp = Wb + (size_t)(kt + 1) * 32 + kc;
            uint32_t da = sa + (uint32_t)(nb * SMS + r0 * 36 + kc) * 4;
            uint32_t db = sb + (uint32_t)(nb * SMS + r0 * 36 + kc) * 4;
#pragma unroll
            for (int i = 0; i < 4; i++) {
                CP_ASYNC16(da + i * (16 * 36 * 4), ap + (size_t)(r0 + 16 * i) * lda);
                CP_ASYNC16(db + i * (16 * 36 * 4), wp + (size_t)(r0 + 16 * i) * ldw);
            }
            CP_COMMIT();
            CP_WAIT(1);
        } else {
            CP_WAIT(0);
        }
        __syncthreads();

        const float* as = As[cur];
        const float* bs = Bs[cur];
#pragma unroll
        for (int ks = 0; ks < 4; ks++) {
            const int kk = ks * 8;
            uint32_t a[2][4], b[4][2];
#pragma unroll
            for (int mt = 0; mt < 2; mt++) {
                int mb = wm * 32 + mt * 16;
                a[mt][0] = __float_as_uint(as[(mb + g) * 36 + kk + c]);
                a[mt][1] = __float_as_uint(as[(mb + g + 8) * 36 + kk + c]);
                a[mt][2] = __float_as_uint(as[(mb + g) * 36 + kk + c + 4]);
                a[mt][3] = __float_as_uint(as[(mb + g + 8) * 36 + kk + c + 4]);
            }
#pragma unroll
            for (int nt = 0; nt < 4; nt++) {
                int nb2 = wn * 32 + nt * 8;
                b[nt][0] = __float_as_uint(bs[(nb2 + g) * 36 + kk + c]);
                b[nt][1] = __float_as_uint(bs[(nb2 + g) * 36 + kk + c + 4]);
            }
#pragma unroll
            for (int mt = 0; mt < 2; mt++)
#pragma unroll
                for (int nt = 0; nt < 4; nt++)
                    MMA_TF32(acc[mt][nt], a[mt][0], a[mt][1], a[mt][2], a[mt][3],
                             b[nt][0], b[nt][1]);
        }
        __syncthreads();
    }

#pragma unroll
    for (int mt = 0; mt < 2; mt++) {
        int row0 = bm + wm * 32 + mt * 16 + g;
#pragma unroll
        for (int nt = 0; nt < 4; nt++) {
            int col = bn + wn * 32 + nt * 8 + c * 2;
            float b0 = bias[col], b1 = bias[col + 1];
            float v0 = acc[mt][nt][0] + b0;
            float v1 = acc[mt][nt][1] + b1;
            float v2 = acc[mt][nt][2] + b0;
            float v3 = acc[mt][nt][3] + b1;
            if (DO_RELU) {
                v0 = fmaxf(v0, 0.f); v1 = fmaxf(v1, 0.f);
                v2 = fmaxf(v2, 0.f); v3 = fmaxf(v3, 0.f);
            }
            if (DO_ROUND) {
                v0 = to_tf32(v0); v1 = to_tf32(v1);
                v2 = to_tf32(v2); v3 = to_tf32(v3);
            }
            *(float2*)&C[(size_t)row0 * ldc + col] = make_float2(v0, v1);
            *(float2*)&C[(size_t)(row0 + 8) * ldc + col] = make_float2(v2, v3);
        }
    }
}

// ---------------- big GEMM: BM=128, BN=128, 256 thr, 3-stage -----------------
// 8 warps: wm in {0,1} x wn in {0..3}; warp tile 64x32.
#define STB 9216   // floats per stage (256 rows * 36)
template<int DO_RELU, int DO_ROUND>
__global__ void __launch_bounds__(256)
gemm_big(const float* __restrict__ A, int lda,
         const float* __restrict__ W, int ldw,
         const float* __restrict__ bias,
         float* __restrict__ C, int ldc, int K)
{
    extern __shared__ float smb[];

    const int tid = threadIdx.x;
    const int warp = tid >> 5, lane = tid & 31;
    const int wm = warp >> 2, wn = warp & 3;
    const int g = lane >> 2, c = lane & 3;
    const int bm = blockIdx.y * 128, bn = blockIdx.x * 128;

    const float* Ab = A + (size_t)bm * lda;
    const float* Wb = W + (size_t)bn * ldw;
    const uint32_t sbase = (uint32_t)__cvta_generic_to_shared(smb);

    float acc[4][4][4];
#pragma unroll
    for (int mt = 0; mt < 4; mt++)
#pragma unroll
        for (int nt = 0; nt < 4; nt++)
#pragma unroll
            for (int q = 0; q < 4; q++) acc[mt][nt][q] = 0.f;

    const int KT = K >> 5;

    // tile issue: 256 rows x 8 float4 chunks = 2048 chunks, 8 per thread
    auto issue = [&](int kt, int stage) {
        const int off = kt * 32;
        const uint32_t sb = sbase + (uint32_t)stage * (STB * 4);
#pragma unroll
        for (int i = 0; i < 8; i++) {
            int q = i * 256 + tid;
            int row = q >> 3, kc = (q & 7) * 4;
            const float* src = (row < 128)
                ? Ab + (size_t)row * lda + off + kc
                : Wb + (size_t)(row - 128) * ldw + off + kc;
            CP_ASYNC16(sb + (uint32_t)(row * 36 + kc) * 4, src);
        }
        CP_COMMIT();
    };

    issue(0, 0);
    if (KT > 1) issue(1, 1);

    for (int kt = 0; kt < KT; kt++) {
        if (kt + 1 < KT) { CP_WAIT(1); } else { CP_WAIT(0); }
        __syncthreads();
        if (kt + 2 < KT) issue(kt + 2, (kt + 2) % 3);

        const float* st = smb + (size_t)(kt % 3) * STB;
        const float* as = st;                 // A rows 0..127
        const float* bs = st + 128 * 36;      // B rows 0..127
#pragma unroll
        for (int ks = 0; ks < 4; ks++) {
            const int kk = ks * 8;
            uint32_t a[4][4], b[4][2];
#pragma unroll
            for (int mt = 0; mt < 4; mt++) {
                int mb = wm * 64 + mt * 16;
                a[mt][0] = __float_as_uint(as[(mb + g) * 36 + kk + c]);
                a[mt][1] = __float_as_uint(as[(mb + g + 8) * 36 + kk + c]);
                a[mt][2] = __float_as_uint(as[(mb + g) * 36 + kk + c + 4]);
                a[mt][3] = __float_as_uint(as[(mb + g + 8) * 36 + kk + c + 4]);
            }
#pragma unroll
            for (int nt = 0; nt < 4; nt++) {
                int nb = wn * 32 + nt * 8;
                b[nt][0] = __float_as_uint(bs[(nb + g) * 36 + kk + c]);
                b[nt][1] = __float_as_uint(bs[(nb + g) * 36 + kk + c + 4]);
            }
#pragma unroll
            for (int mt = 0; mt < 4; mt++)
#pragma unroll
                for (int nt = 0; nt < 4; nt++)
                    MMA_TF32(acc[mt][nt], a[mt][0], a[mt][1], a[mt][2], a[mt][3],
                             b[nt][0], b[nt][1]);
        }
    }

#pragma unroll
    for (int mt = 0; mt < 4; mt++) {
        int row0 = bm + wm * 64 + mt * 16 + g;
#pragma unroll
        for (int nt = 0; nt < 4; nt++) {
            int col = bn + wn * 32 + nt * 8 + c * 2;
            float b0 = bias[col], b1 = bias[col + 1];
            float v0 = acc[mt][nt][0] + b0;
            float v1 = acc[mt][nt][1] + b1;
            float v2 = acc[mt][nt][2] + b0;
            float v3 = acc[mt][nt][3] + b1;
            if (DO_RELU) {
                v0 = fmaxf(v0, 0.f); v1 = fmaxf(v1, 0.f);
                v2 = fmaxf(v2, 0.f); v3 = fmaxf(v3, 0.f);
            }
            if (DO_ROUND) {
                v0 = to_tf32(v0); v1 = to_tf32(v1);
                v2 = to_tf32(v2); v3 = to_tf32(v3);
            }
            *(float2*)&C[(size_t)row0 * ldc + col] = make_float2(v0, v1);
            *(float2*)&C[(size_t)(row0 + 8) * ldc + col] = make_float2(v2, v3);
        }
    }
}
#define SMB_BYTES (3 * STB * 4)

// ---------------- embedding gather + mean: float4, 2 samples/warp ------------
__global__ void __launch_bounds__(256)
embed_mean(const float* __restrict__ tables, const int* __restrict__ lS_i,
           float* __restrict__ feat)
{
    int gw = (blockIdx.x * blockDim.x + threadIdx.x) >> 5;
    int lane = threadIdx.x & 31;
    int p = gw * 2 + (lane >> 4);          // sample pair index
    int l16 = lane & 15;
    if (p >= N_TABLES * BATCH) return;
    int t = p / BATCH;
    int b = p - t * BATCH;

    const int* idx = lS_i + (size_t)t * BATCH * L + (size_t)b * L;
    const float* tab = tables + (size_t)t * ROWS * D;

    int i0 = idx[0], i1 = idx[1], i2 = idx[2], i3 = idx[3];
    float4 v0 = ((const float4*)(tab + (size_t)i0 * D))[l16];
    float4 v1 = ((const float4*)(tab + (size_t)i1 * D))[l16];
    float4 v2 = ((const float4*)(tab + (size_t)i2 * D))[l16];
    float4 v3 = ((const float4*)(tab + (size_t)i3 * D))[l16];

    float4 o;
    o.x = to_tf32(((v0.x + v1.x) + (v2.x + v3.x)) * 0.25f);
    o.y = to_tf32(((v0.y + v1.y) + (v2.y + v3.y)) * 0.25f);
    o.z = to_tf32(((v0.z + v1.z) + (v2.z + v3.z)) * 0.25f);
    o.w = to_tf32(((v0.w + v1.w) + (v2.w + v3.w)) * 0.25f);
    ((float4*)(feat + (size_t)b * FEAT_LD + (size_t)(1 + t) * D))[l16] = o;
}

// ---------------- tensor-core interaction ------------------------------------
#define TS 68
__global__ void __launch_bounds__(128)
interact_mma(const float* __restrict__ feat, float* __restrict__ R)
{
    __shared__ float Ts[4][32 * TS];
    const int warp = threadIdx.x >> 5;
    const int lane = threadIdx.x & 31;
    const int b = blockIdx.x * 4 + warp;
    const int g = lane >> 2, c = lane & 3;

    float* tw = Ts[warp];
    const float* f = feat + (size_t)b * FEAT_LD;
    for (int q = lane; q < 432; q += 32) {
        int fi = q >> 4, kc = (q & 15) * 4;
        *(float4*)&tw[fi * TS + kc] = *(const float4*)&f[fi * D + kc];
    }
    __syncwarp();

    float acc[2][4][4];
#pragma unroll
    for (int mt = 0; mt < 2; mt++)
#pragma unroll
        for (int nt = 0; nt < 4; nt++)
#pragma unroll
            for (int q = 0; q < 4; q++) acc[mt][nt][q] = 0.f;

#pragma unroll
    for (int ks = 0; ks < 8; ks++) {
        const int kk = ks * 8;
        uint32_t a[2][4], bfr[4][2];
#pragma unroll
        for (int mt = 0; mt < 2; mt++) {
            int mb = mt * 16;
            a[mt][0] = __float_as_uint(tw[(mb + g) * TS + kk + c]);
            a[mt][1] = __float_as_uint(tw[(mb + g + 8) * TS + kk + c]);
            a[mt][2] = __float_as_uint(tw[(mb + g) * TS + kk + c + 4]);
            a[mt][3] = __float_as_uint(tw[(mb + g + 8) * TS + kk + c + 4]);
        }
#pragma unroll
        for (int nt = 0; nt < 4; nt++) {
            int nb = nt * 8;
            bfr[nt][0] = __float_as_uint(tw[(nb + g) * TS + kk + c]);
            bfr[nt][1] = __float_as_uint(tw[(nb + g) * TS + kk + c + 4]);
        }
#pragma unroll
        for (int mt = 0; mt < 2; mt++)
#pragma unroll
            for (int nt = 0; nt < 4; nt++)
                MMA_TF32(acc[mt][nt], a[mt][0], a[mt][1], a[mt][2], a[mt][3],
                         bfr[nt][0], bfr[nt][1]);
    }

    float* r = R + (size_t)b * RLD;
    for (int k = lane; k < D; k += 32) r[k] = tw[k];
    if (lane == 0) r[415] = 0.f;

#pragma unroll
    for (int mt = 0; mt < 2; mt++) {
        int row0 = mt * 16 + g;
#pragma unroll
        for (int nt = 0; nt < 4; nt++) {
            int col = nt * 8 + c * 2;
#pragma unroll
            for (int q = 0; q < 4; q++) {
                int ri = row0 + ((q >> 1) << 3);
                int cj = col + (q & 1);
                if (cj < ri && ri < NFEAT)
                    r[64 + ri * (ri - 1) / 2 + cj] = to_tf32(acc[mt][nt][q]);
            }
        }
    }
}

// ---------------- final layer ------------------------------------------------
__global__ void __launch_bounds__(256)
top_final(const float* __restrict__ A, const float* __restrict__ w,
          const float* __restrict__ bias, float* __restrict__ out)
{
    __shared__ float ws[256];
    int tid = threadIdx.x;
    ws[tid] = w[tid];
    __syncthreads();

    int warp = tid >> 5, lane = tid & 31;
    int row = blockIdx.x * 8 + warp;
    const float* a = A + (size_t)row * 256;
    float s = 0.f;
#pragma unroll
    for (int k = 0; k < 8; k++) s += a[lane + k * 32] * ws[lane + k * 32];
#pragma unroll
    for (int o = 16; o > 0; o >>= 1) s += __shfl_xor_sync(0xffffffffu, s, o);
    if (lane == 0) out[row] = s + bias[0];
}

// ---------------- launch ------------------------------------------------------
extern "C" void kernel_launch(void* const* d_in, const int* in_sizes, int n_in,
                              void* d_out, int out_size)
{
    const float* dense_x = (const float*)d_in[0];
    const int*   lS_i    = (const int*)d_in[2];
    const float* tables  = (const float*)d_in[3];
    const float* bw0 = (const float*)d_in[4];
    const float* bb0 = (const float*)d_in[5];
    const float* bw1 = (const float*)d_in[6];
    const float* bb1 = (const float*)d_in[7];
    const float* bw2 = (const float*)d_in[8];
    const float* bb2 = (const float*)d_in[9];
    const float* tw0 = (const float*)d_in[10];
    const float* tb0 = (const float*)d_in[11];
    const float* tw1 = (const float*)d_in[12];
    const float* tb1 = (const float*)d_in[13];
    const float* tw2 = (const float*)d_in[14];
    const float* tb2 = (const float*)d_in[15];
    float* out = (float*)d_out;

    float *p_b0, *p_b1, *p_feat, *p_R, *p_t0, *p_t1;
    float *p_dx, *p_w0, *p_w1, *p_w2, *p_tw0, *p_tw1;
    cudaGetSymbolAddress((void**)&p_b0,   g_b0);
    cudaGetSymbolAddress((void**)&p_b1,   g_b1);
    cudaGetSymbolAddress((void**)&p_feat, g_feat);
    cudaGetSymbolAddress((void**)&p_R,    g_R);
    cudaGetSymbolAddress((void**)&p_t0,   g_t0);
    cudaGetSymbolAddress((void**)&p_t1,   g_t1);
    cudaGetSymbolAddress((void**)&p_dx,   g_dx);
    cudaGetSymbolAddress((void**)&p_w0,   g_w0);
    cudaGetSymbolAddress((void**)&p_w1,   g_w1);
    cudaGetSymbolAddress((void**)&p_w2,   g_w2);
    cudaGetSymbolAddress((void**)&p_tw0,  g_tw0);
    cudaGetSymbolAddress((void**)&p_tw1,  g_tw1);

    cudaFuncSetAttribute(gemm_big<1, 1>,
        cudaFuncAttributeMaxDynamicSharedMemorySize, SMB_BYTES);
    cudaFuncSetAttribute(gemm_big<1, 0>,
        cudaFuncAttributeMaxDynamicSharedMemorySize, SMB_BYTES);

    // fork: embed on side stream, MLP chain on main stream
    cudaStream_t s2;
    cudaStreamCreateWithFlags(&s2, cudaStreamNonBlocking);
    cudaEvent_t e0, e1;
    cudaEventCreateWithFlags(&e0, cudaEventDisableTiming);
    cudaEventCreateWithFlags(&e1, cudaEventDisableTiming);

    cudaEventRecord(e0, 0);
    cudaStreamWaitEvent(s2, e0, 0);
    {
        int pairs = N_TABLES * BATCH;          // 2 per warp
        int warps = (pairs + 1) / 2;
        embed_mean<<<(warps + 7) / 8, 256, 0, s2>>>(tables, lS_i, p_feat);
    }
    cudaEventRecord(e1, s2);

    // main stream: prep + bottom MLP
    prep<<<(PREP_TOTAL + 255) / 256, 256>>>(dense_x, bw0, bw1, bw2, tw0, tw1);
    gemm_cp<1, 1><<<dim3(8, 128), 128>>>(p_dx, 32, p_w0, 32, bb0, p_b0, 512, 32);
    gemm_big<1, 1><<<dim3(2, 64), 256, SMB_BYTES>>>(p_b0, 512, p_w1, 512, bb1, p_b1, 256, 512);
    gemm_cp<1, 1><<<dim3(1, 128), 128>>>(p_b1, 256, p_w2, 256, bb2, p_feat, FEAT_LD, 256);

    // join embed branch
    cudaStreamWaitEvent(0, e1, 0);

    // interaction -> R (stride 416)
    interact_mma<<<BATCH / 4, 128>>>(p_feat, p_R);

    // top MLP
    gemm_big<1, 1><<<dim3(4, 64), 256, SMB_BYTES>>>(p_R, RLD, p_tw0, RLD, tb0, p_t0, 512, RLD);
    gemm_big<1, 0><<<dim3(2, 64), 256, SMB_BYTES>>>(p_t0, 512, p_tw1, 512, tb1, p_t1, 256, 512);
    top_final<<<BATCH / 8, 256>>>(p_t1, tw2, tb2, out);
}

// round 7
// speedup vs baseline: 1.7635x; 1.0199x over previous
#include <cuda_runtime.h>
#include <math.h>
#include <stdint.h>

#define N_TABLES 26
#define ROWS 100001
#define D 64
#define BATCH 8192
#define L 4
#define NFEAT 27
#define FEAT_LD (NFEAT * D)  // 1728
#define NPAIR 351
#define RLD 416              // padded R stride (K for top0)

// ---------------- scratch (device globals) ----------------------------------
__device__ float g_b0[BATCH * 512];
__device__ float g_b1[BATCH * 256];
__device__ float g_feat[BATCH * FEAT_LD];
__device__ float g_R[BATCH * RLD];
__device__ float g_t0[BATCH * 512];
__device__ float g_t1[BATCH * 256];
// pre-rounded / padded inputs
__device__ float g_dx[BATCH * 32];
__device__ float g_w0[512 * 32];
__device__ float g_w1[256 * 512];
__device__ float g_w2[64 * 256];
__device__ float g_tw0[512 * RLD];
__device__ float g_tw1[256 * 512];

__device__ __forceinline__ float to_tf32(float v) {
    float r;
    asm("cvt.rna.tf32.f32 %0, %1;" : "=f"(r) : "f"(v));
    return r;
}

#define CP_ASYNC16(dst, src) \
    asm volatile("cp.async.cg.shared.global [%0], [%1], 16;\n" :: "r"(dst), "l"(src))
#define CP_COMMIT() asm volatile("cp.async.commit_group;\n")
#define CP_WAIT(n)  asm volatile("cp.async.wait_group %0;\n" :: "n"(n))

#define MMA_TF32(acc, a0, a1, a2, a3, b0, b1)                                  \
    asm volatile(                                                              \
        "mma.sync.aligned.m16n8k8.row.col.f32.tf32.tf32.f32 "                  \
        "{%0,%1,%2,%3}, {%4,%5,%6,%7}, {%8,%9}, {%0,%1,%2,%3};\n"              \
        : "+f"(acc[0]), "+f"(acc[1]), "+f"(acc[2]), "+f"(acc[3])               \
        : "r"(a0), "r"(a1), "r"(a2), "r"(a3), "r"(b0), "r"(b1))

#define LDSM_X4(r, addr)                                                       \
    asm volatile("ldmatrix.sync.aligned.m8n8.x4.shared.b16 {%0,%1,%2,%3}, [%4];" \
        : "=r"((r)[0]), "=r"((r)[1]), "=r"((r)[2]), "=r"((r)[3]) : "r"(addr))

// ---------------- prep: round weights / pad dense to tf32 --------------------
__global__ void __launch_bounds__(256)
prep(const float* __restrict__ dx, const float* __restrict__ bw0,
     const float* __restrict__ bw1, const float* __restrict__ bw2,
     const float* __restrict__ tw0, const float* __restrict__ tw1)
{
    int i = blockIdx.x * 256 + threadIdx.x;
    if (i < BATCH * 32) {
        int r = i >> 5, c = i & 31;
        g_dx[i] = (c < 13) ? to_tf32(dx[r * 13 + c]) : 0.f;
        return;
    }
    i -= BATCH * 32;
    if (i < 512 * 32) {
        int r = i >> 5, c = i & 31;
        g_w0[i] = (c < 13) ? to_tf32(bw0[r * 13 + c]) : 0.f;
        return;
    }
    i -= 512 * 32;
    if (i < 512 * RLD) {
        int r = i / RLD, c = i - r * RLD;
        g_tw0[i] = (c < 415) ? to_tf32(tw0[r * 415 + c]) : 0.f;
        return;
    }
    i -= 512 * RLD;
    if (i < 256 * 512) { g_w1[i] = to_tf32(bw1[i]); return; }
    i -= 256 * 512;
    if (i < 256 * 512) { g_tw1[i] = to_tf32(tw1[i]); return; }
    i -= 256 * 512;
    if (i < 64 * 256) { g_w2[i] = to_tf32(bw2[i]); return; }
}
#define PREP_TOTAL (BATCH*32 + 512*32 + 512*RLD + 256*512 + 256*512 + 64*256)

// ---------------- R4 cp.async GEMM (BM=64) — bot0, bot2 ----------------------
#define SMS 2304  // 64*36 floats per buffer
template<int DO_RELU, int DO_ROUND>
__global__ void __launch_bounds__(128)
gemm_cp(const float* __restrict__ A, int lda,
        const float* __restrict__ W, int ldw,
        const float* __restrict__ bias,
        float* __restrict__ C, int ldc, int K)
{
    __shared__ float As[2][SMS];
    __shared__ float Bs[2][SMS];

    const int tid = threadIdx.x;
    const int warp = tid >> 5, lane = tid & 31;
    const int wm = warp >> 1, wn = warp & 1;
    const int g = lane >> 2, c = lane & 3;
    const int bm = blockIdx.y * 64, bn = blockIdx.x * 64;

    const float* Ab = A + (size_t)bm * lda;
    const float* Wb = W + (size_t)bn * ldw;

    const int r0 = tid >> 3;
    const int kc = (tid & 7) * 4;

    const uint32_t sa = (uint32_t)__cvta_generic_to_shared(&As[0][0]);
    const uint32_t sb = (uint32_t)__cvta_generic_to_shared(&Bs[0][0]);

    float acc[2][4][4];
#pragma unroll
    for (int mt = 0; mt < 2; mt++)
#pragma unroll
        for (int nt = 0; nt < 4; nt++)
#pragma unroll
            for (int q = 0; q < 4; q++) acc[mt][nt][q] = 0.f;

    const int KT = K >> 5;

    {
        const float* ap = Ab + kc;
        const float* wp = Wb + kc;
        uint32_t da = sa + (uint32_t)(r0 * 36 + kc) * 4;
        uint32_t db = sb + (uint32_t)(r0 * 36 + kc) * 4;
#pragma unroll
        for (int i = 0; i < 4; i++) {
            CP_ASYNC16(da + i * (16 * 36 * 4), ap + (size_t)(r0 + 16 * i) * lda);
            CP_ASYNC16(db + i * (16 * 36 * 4), wp + (size_t)(r0 + 16 * i) * ldw);
        }
        CP_COMMIT();
    }

    for (int kt = 0; kt < KT; kt++) {
        const int cur = kt & 1;
        if (kt + 1 < KT) {
            const int nb = cur ^ 1;
            const float* ap = Ab + (size_t)(kt + 1) * 32 + kc;
            const float* wp = Wb + (size_t)(kt + 1) * 32 + kc;
            uint32_t da = sa + (uint32_t)(nb * SMS + r0 * 36 + kc) * 4;
            uint32_t db = sb + (uint32_t)(nb * SMS + r0 * 36 + kc) * 4;
#pragma unroll
            for (int i = 0; i < 4; i++) {
                CP_ASYNC16(da + i * (16 * 36 * 4), ap + (size_t)(r0 + 16 * i) * lda);
                CP_ASYNC16(db + i * (16 * 36 * 4), wp + (size_t)(r0 + 16 * i) * ldw);
            }
            CP_COMMIT();
            CP_WAIT(1);
        } else {
            CP_WAIT(0);
        }
        __syncthreads();

        const float* as = As[cur];
        const float* bs = Bs[cur];
#pragma unroll
        for (int ks = 0; ks < 4; ks++) {
            const int kk = ks * 8;
            uint32_t a[2][4], b[4][2];
#pragma unroll
            for (int mt = 0; mt < 2; mt++) {
                int mb = wm * 32 + mt * 16;
                a[mt][0] = __float_as_uint(as[(mb + g) * 36 + kk + c]);
                a[mt][1] = __float_as_uint(as[(mb + g + 8) * 36 + kk + c]);
                a[mt][2] = __float_as_uint(as[(mb + g) * 36 + kk + c + 4]);
                a[mt][3] = __float_as_uint(as[(mb + g + 8) * 36 + kk + c + 4]);
            }
#pragma unroll
            for (int nt = 0; nt < 4; nt++) {
                int nb2 = wn * 32 + nt * 8;
                b[nt][0] = __float_as_uint(bs[(nb2 + g) * 36 + kk + c]);
                b[nt][1] = __float_as_uint(bs[(nb2 + g) * 36 + kk + c + 4]);
            }
#pragma unroll
            for (int mt = 0; mt < 2; mt++)
#pragma unroll
                for (int nt = 0; nt < 4; nt++)
                    MMA_TF32(acc[mt][nt], a[mt][0], a[mt][1], a[mt][2], a[mt][3],
                             b[nt][0], b[nt][1]);
        }
        __syncthreads();
    }

#pragma unroll
    for (int mt = 0; mt < 2; mt++) {
        int row0 = bm + wm * 32 + mt * 16 + g;
#pragma unroll
        for (int nt = 0; nt < 4; nt++) {
            int col = bn + wn * 32 + nt * 8 + c * 2;
            float b0 = bias[col], b1 = bias[col + 1];
            float v0 = acc[mt][nt][0] + b0;
            float v1 = acc[mt][nt][1] + b1;
            float v2 = acc[mt][nt][2] + b0;
            float v3 = acc[mt][nt][3] + b1;
            if (DO_RELU) {
                v0 = fmaxf(v0, 0.f); v1 = fmaxf(v1, 0.f);
                v2 = fmaxf(v2, 0.f); v3 = fmaxf(v3, 0.f);
            }
            if (DO_ROUND) {
                v0 = to_tf32(v0); v1 = to_tf32(v1);
                v2 = to_tf32(v2); v3 = to_tf32(v3);
            }
            *(float2*)&C[(size_t)row0 * ldc + col] = make_float2(v0, v1);
            *(float2*)&C[(size_t)(row0 + 8) * ldc + col] = make_float2(v2, v3);
        }
    }
}

// ---------------- big GEMM: BM=128, BN=128, 256 thr, 3-stage, ldmatrix -------
// 8 warps: wm in {0,1} x wn in {0..3}; warp tile 64x32. 2 CTAs/SM.
#define STB 9216   // floats per stage (256 rows * 36)
template<int DO_RELU, int DO_ROUND>
__global__ void __launch_bounds__(256, 2)
gemm_big(const float* __restrict__ A, int lda,
         const float* __restrict__ W, int ldw,
         const float* __restrict__ bias,
         float* __restrict__ C, int ldc, int K)
{
    extern __shared__ float smb[];

    const int tid = threadIdx.x;
    const int warp = tid >> 5, lane = tid & 31;
    const int wm = warp >> 2, wn = warp & 3;
    const int g = lane >> 2, c = lane & 3;
    const int bm = blockIdx.y * 128, bn = blockIdx.x * 128;

    const float* Ab = A + (size_t)bm * lda;
    const float* Wb = W + (size_t)bn * ldw;
    const uint32_t sbase = (uint32_t)__cvta_generic_to_shared(smb);

    // ldmatrix per-thread byte offsets (within a stage)
    const int lane15 = lane & 15;
    const int lanehi = lane >> 4;          // 0/1 -> k half for A, row-block for B
    uint32_t aoff[4], boff[2];
#pragma unroll
    for (int mt = 0; mt < 4; mt++)
        aoff[mt] = (uint32_t)(((wm * 64 + mt * 16 + lane15) * 36 + lanehi * 4) * 4);
#pragma unroll
    for (int p = 0; p < 2; p++)
        boff[p] = (uint32_t)((128 * 36 +
                   (wn * 32 + p * 16 + lanehi * 8 + (lane & 7)) * 36 +
                   ((lane >> 3) & 1) * 4) * 4);

    float acc[4][4][4];
#pragma unroll
    for (int mt = 0; mt < 4; mt++)
#pragma unroll
        for (int nt = 0; nt < 4; nt++)
#pragma unroll
            for (int q = 0; q < 4; q++) acc[mt][nt][q] = 0.f;

    const int KT = K >> 5;

    auto issue = [&](int kt, int stage) {
        const int off = kt * 32;
        const uint32_t sb = sbase + (uint32_t)stage * (STB * 4);
#pragma unroll
        for (int i = 0; i < 8; i++) {
            int q = i * 256 + tid;
            int row = q >> 3, kc = (q & 7) * 4;
            const float* src = (row < 128)
                ? Ab + (size_t)row * lda + off + kc
                : Wb + (size_t)(row - 128) * ldw + off + kc;
            CP_ASYNC16(sb + (uint32_t)(row * 36 + kc) * 4, src);
        }
        CP_COMMIT();
    };

    issue(0, 0);
    if (KT > 1) issue(1, 1);

    for (int kt = 0; kt < KT; kt++) {
        if (kt + 1 < KT) { CP_WAIT(1); } else { CP_WAIT(0); }
        __syncthreads();
        if (kt + 2 < KT) issue(kt + 2, (kt + 2) % 3);

        const uint32_t sst = sbase + (uint32_t)((kt % 3) * (STB * 4));
#pragma unroll
        for (int ks = 0; ks < 4; ks++) {
            uint32_t a[4][4], b[2][4];
#pragma unroll
            for (int mt = 0; mt < 4; mt++)
                LDSM_X4(a[mt], sst + aoff[mt] + ks * 32);
#pragma unroll
            for (int p = 0; p < 2; p++)
                LDSM_X4(b[p], sst + boff[p] + ks * 32);
#pragma unroll
            for (int mt = 0; mt < 4; mt++)
#pragma unroll
                for (int nt = 0; nt < 4; nt++)
                    MMA_TF32(acc[mt][nt], a[mt][0], a[mt][1], a[mt][2], a[mt][3],
                             b[nt >> 1][(nt & 1) * 2], b[nt >> 1][(nt & 1) * 2 + 1]);
        }
    }

#pragma unroll
    for (int mt = 0; mt < 4; mt++) {
        int row0 = bm + wm * 64 + mt * 16 + g;
#pragma unroll
        for (int nt = 0; nt < 4; nt++) {
            int col = bn + wn * 32 + nt * 8 + c * 2;
            float b0 = bias[col], b1 = bias[col + 1];
            float v0 = acc[mt][nt][0] + b0;
            float v1 = acc[mt][nt][1] + b1;
            float v2 = acc[mt][nt][2] + b0;
            float v3 = acc[mt][nt][3] + b1;
            if (DO_RELU) {
                v0 = fmaxf(v0, 0.f); v1 = fmaxf(v1, 0.f);
                v2 = fmaxf(v2, 0.f); v3 = fmaxf(v3, 0.f);
            }
            if (DO_ROUND) {
                v0 = to_tf32(v0); v1 = to_tf32(v1);
                v2 = to_tf32(v2); v3 = to_tf32(v3);
            }
            *(float2*)&C[(size_t)row0 * ldc + col] = make_float2(v0, v1);
            *(float2*)&C[(size_t)(row0 + 8) * ldc + col] = make_float2(v2, v3);
        }
    }
}
#define SMB_BYTES (3 * STB * 4)

// ---------------- embedding gather + mean: float4, 2 samples/warp ------------
__global__ void __launch_bounds__(256)
embed_mean(const float* __restrict__ tables, const int* __restrict__ lS_i,
           float* __restrict__ feat)
{
    int gw = (blockIdx.x * blockDim.x + threadIdx.x) >> 5;
    int lane = threadIdx.x & 31;
    int p = gw * 2 + (lane >> 4);
    int l16 = lane & 15;
    if (p >= N_TABLES * BATCH) return;
    int t = p / BATCH;
    int b = p - t * BATCH;

    const int* idx = lS_i + (size_t)t * BATCH * L + (size_t)b * L;
    const float* tab = tables + (size_t)t * ROWS * D;

    int i0 = idx[0], i1 = idx[1], i2 = idx[2], i3 = idx[3];
    float4 v0 = ((const float4*)(tab + (size_t)i0 * D))[l16];
    float4 v1 = ((const float4*)(tab + (size_t)i1 * D))[l16];
    float4 v2 = ((const float4*)(tab + (size_t)i2 * D))[l16];
    float4 v3 = ((const float4*)(tab + (size_t)i3 * D))[l16];

    float4 o;
    o.x = to_tf32(((v0.x + v1.x) + (v2.x + v3.x)) * 0.25f);
    o.y = to_tf32(((v0.y + v1.y) + (v2.y + v3.y)) * 0.25f);
    o.z = to_tf32(((v0.z + v1.z) + (v2.z + v3.z)) * 0.25f);
    o.w = to_tf32(((v0.w + v1.w) + (v2.w + v3.w)) * 0.25f);
    ((float4*)(feat + (size_t)b * FEAT_LD + (size_t)(1 + t) * D))[l16] = o;
}

// ---------------- tensor-core interaction ------------------------------------
#define TS 68
__global__ void __launch_bounds__(128)
interact_mma(const float* __restrict__ feat, float* __restrict__ R)
{
    __shared__ float Ts[4][32 * TS];
    const int warp = threadIdx.x >> 5;
    const int lane = threadIdx.x & 31;
    const int b = blockIdx.x * 4 + warp;
    const int g = lane >> 2, c = lane & 3;

    float* tw = Ts[warp];
    const float* f = feat + (size_t)b * FEAT_LD;
    for (int q = lane; q < 432; q += 32) {
        int fi = q >> 4, kc = (q & 15) * 4;
        *(float4*)&tw[fi * TS + kc] = *(const float4*)&f[fi * D + kc];
    }
    __syncwarp();

    float acc[2][4][4];
#pragma unroll
    for (int mt = 0; mt < 2; mt++)
#pragma unroll
        for (int nt = 0; nt < 4; nt++)
#pragma unroll
            for (int q = 0; q < 4; q++) acc[mt][nt][q] = 0.f;

#pragma unroll
    for (int ks = 0; ks < 8; ks++) {
        const int kk = ks * 8;
        uint32_t a[2][4], bfr[4][2];
#pragma unroll
        for (int mt = 0; mt < 2; mt++) {
            int mb = mt * 16;
            a[mt][0] = __float_as_uint(tw[(mb + g) * TS + kk + c]);
            a[mt][1] = __float_as_uint(tw[(mb + g + 8) * TS + kk + c]);
            a[mt][2] = __float_as_uint(tw[(mb + g) * TS + kk + c + 4]);
            a[mt][3] = __float_as_uint(tw[(mb + g + 8) * TS + kk + c + 4]);
        }
#pragma unroll
        for (int nt = 0; nt < 4; nt++) {
            int nb = nt * 8;
            bfr[nt][0] = __float_as_uint(tw[(nb + g) * TS + kk + c]);
            bfr[nt][1] = __float_as_uint(tw[(nb + g) * TS + kk + c + 4]);
        }
#pragma unroll
        for (int mt = 0; mt < 2; mt++)
#pragma unroll
            for (int nt = 0; nt < 4; nt++)
                MMA_TF32(acc[mt][nt], a[mt][0], a[mt][1], a[mt][2], a[mt][3],
                         bfr[nt][0], bfr[nt][1]);
    }

    float* r = R + (size_t)b * RLD;
    for (int k = lane; k < D; k += 32) r[k] = tw[k];
    if (lane == 0) r[415] = 0.f;

#pragma unroll
    for (int mt = 0; mt < 2; mt++) {
        int row0 = mt * 16 + g;
#pragma unroll
        for (int nt = 0; nt < 4; nt++) {
            int col = nt * 8 + c * 2;
#pragma unroll
            for (int q = 0; q < 4; q++) {
                int ri = row0 + ((q >> 1) << 3);
                int cj = col + (q & 1);
                if (cj < ri && ri < NFEAT)
                    r[64 + ri * (ri - 1) / 2 + cj] = to_tf32(acc[mt][nt][q]);
            }
        }
    }
}

// ---------------- final layer ------------------------------------------------
__global__ void __launch_bounds__(256)
top_final(const float* __restrict__ A, const float* __restrict__ w,
          const float* __restrict__ bias, float* __restrict__ out)
{
    __shared__ float ws[256];
    int tid = threadIdx.x;
    ws[tid] = w[tid];
    __syncthreads();

    int warp = tid >> 5, lane = tid & 31;
    int row = blockIdx.x * 8 + warp;
    const float* a = A + (size_t)row * 256;
    float s = 0.f;
#pragma unroll
    for (int k = 0; k < 8; k++) s += a[lane + k * 32] * ws[lane + k * 32];
#pragma unroll
    for (int o = 16; o > 0; o >>= 1) s += __shfl_xor_sync(0xffffffffu, s, o);
    if (lane == 0) out[row] = s + bias[0];
}

// ---------------- launch ------------------------------------------------------
extern "C" void kernel_launch(void* const* d_in, const int* in_sizes, int n_in,
                              void* d_out, int out_size)
{
    const float* dense_x = (const float*)d_in[0];
    const int*   lS_i    = (const int*)d_in[2];
    const float* tables  = (const float*)d_in[3];
    const float* bw0 = (const float*)d_in[4];
    const float* bb0 = (const float*)d_in[5];
    const float* bw1 = (const float*)d_in[6];
    const float* bb1 = (const float*)d_in[7];
    const float* bw2 = (const float*)d_in[8];
    const float* bb2 = (const float*)d_in[9];
    const float* tw0 = (const float*)d_in[10];
    const float* tb0 = (const float*)d_in[11];
    const float* tw1 = (const float*)d_in[12];
    const float* tb1 = (const float*)d_in[13];
    const float* tw2 = (const float*)d_in[14];
    const float* tb2 = (const float*)d_in[15];
    float* out = (float*)d_out;

    float *p_b0, *p_b1, *p_feat, *p_R, *p_t0, *p_t1;
    float *p_dx, *p_w0, *p_w1, *p_w2, *p_tw0, *p_tw1;
    cudaGetSymbolAddress((void**)&p_b0,   g_b0);
    cudaGetSymbolAddress((void**)&p_b1,   g_b1);
    cudaGetSymbolAddress((void**)&p_feat, g_feat);
    cudaGetSymbolAddress((void**)&p_R,    g_R);
    cudaGetSymbolAddress((void**)&p_t0,   g_t0);
    cudaGetSymbolAddress((void**)&p_t1,   g_t1);
    cudaGetSymbolAddress((void**)&p_dx,   g_dx);
    cudaGetSymbolAddress((void**)&p_w0,   g_w0);
    cudaGetSymbolAddress((void**)&p_w1,   g_w1);
    cudaGetSymbolAddress((void**)&p_w2,   g_w2);
    cudaGetSymbolAddress((void**)&p_tw0,  g_tw0);
    cudaGetSymbolAddress((void**)&p_tw1,  g_tw1);

    cudaFuncSetAttribute(gemm_big<1, 1>,
        cudaFuncAttributeMaxDynamicSharedMemorySize, SMB_BYTES);
    cudaFuncSetAttribute(gemm_big<1, 0>,
        cudaFuncAttributeMaxDynamicSharedMemorySize, SMB_BYTES);

    // fork: embed on side stream, MLP chain on main stream
    cudaStream_t s2;
    cudaStreamCreateWithFlags(&s2, cudaStreamNonBlocking);
    cudaEvent_t e0, e1;
    cudaEventCreateWithFlags(&e0, cudaEventDisableTiming);
    cudaEventCreateWithFlags(&e1, cudaEventDisableTiming);

    cudaEventRecord(e0, 0);
    cudaStreamWaitEvent(s2, e0, 0);
    {
        int pairs = N_TABLES * BATCH;
        int warps = (pairs + 1) / 2;
        embed_mean<<<(warps + 7) / 8, 256, 0, s2>>>(tables, lS_i, p_feat);
    }
    cudaEventRecord(e1, s2);

    // main stream: prep + bottom MLP
    prep<<<(PREP_TOTAL + 255) / 256, 256>>>(dense_x, bw0, bw1, bw2, tw0, tw1);
    gemm_cp<1, 1><<<dim3(8, 128), 128>>>(p_dx, 32, p_w0, 32, bb0, p_b0, 512, 32);
    gemm_big<1, 1><<<dim3(2, 64), 256, SMB_BYTES>>>(p_b0, 512, p_w1, 512, bb1, p_b1, 256, 512);
    gemm_cp<1, 1><<<dim3(1, 128), 128>>>(p_b1, 256, p_w2, 256, bb2, p_feat, FEAT_LD, 256);

    // join embed branch
    cudaStreamWaitEvent(0, e1, 0);

    // interaction -> R (stride 416)
    interact_mma<<<BATCH / 4, 128>>>(p_feat, p_R);

    // top MLP
    gemm_big<1, 1><<<dim3(4, 64), 256, SMB_BYTES>>>(p_R, RLD, p_tw0, RLD, tb0, p_t0, 512, RLD);
    gemm_big<1, 0><<<dim3(2, 64), 256, SMB_BYTES>>>(p_t0, 512, p_tw1, 512, tb1, p_t1, 256, 512);
    top_final<<<BATCH / 8, 256>>>(p_t1, tw2, tb2, out);
}